// round 12
// baseline (speedup 1.0000x reference)
#include <cuda_runtime.h>
#include <cuda_fp16.h>
#include <math.h>
#include <stdint.h>

// Problem constants
#define D_MODEL 1024
#define NH      16
#define DK      64
#define BATCH   4
#define TSEQ    2048
#define BT      (BATCH * TSEQ)      // 8192 rows
#define C3      (3 * D_MODEL)       // 3072

// Scratch (allocation-free rule: __device__ globals), all fp16
__device__ __half g_hx[BT * D_MODEL];        // 16 MB  x
__device__ __half g_hw[C3 * D_MODEL];        //  6 MB  W_attn
__device__ __half g_hwo[D_MODEL * D_MODEL];  //  2 MB  W_o
__device__ __half g_qkv[BT * C3];            // 48 MB  QKV
__device__ __half g_hy[BT * D_MODEL];        // 16 MB  attention out

// ---------------------------------------------------------------------------
// helpers
// ---------------------------------------------------------------------------
__device__ __forceinline__ uint32_t h2(float lo, float hi) {
    uint32_t r;
    asm("cvt.rn.f16x2.f32 %0, %1, %2;" : "=r"(r) : "f"(hi), "f"(lo));
    return r;
}

__device__ __forceinline__ void mmah(float c[4], const uint32_t a[4],
                                     uint32_t b0, uint32_t b1) {
    asm volatile(
        "mma.sync.aligned.m16n8k16.row.col.f32.f16.f16.f32 "
        "{%0,%1,%2,%3},{%4,%5,%6,%7},{%8,%9},{%0,%1,%2,%3};"
        : "+f"(c[0]), "+f"(c[1]), "+f"(c[2]), "+f"(c[3])
        : "r"(a[0]), "r"(a[1]), "r"(a[2]), "r"(a[3]), "r"(b0), "r"(b1));
}

__device__ __forceinline__ void ldsm4(uint32_t f[4], uint32_t addr) {
    asm volatile("ldmatrix.sync.aligned.m8n8.x4.shared.b16 {%0,%1,%2,%3}, [%4];"
        : "=r"(f[0]), "=r"(f[1]), "=r"(f[2]), "=r"(f[3]) : "r"(addr));
}

__device__ __forceinline__ void ldsm4t(uint32_t f[4], uint32_t addr) {
    asm volatile("ldmatrix.sync.aligned.m8n8.x4.trans.shared.b16 {%0,%1,%2,%3}, [%4];"
        : "=r"(f[0]), "=r"(f[1]), "=r"(f[2]), "=r"(f[3]) : "r"(addr));
}

__device__ __forceinline__ uint32_t smem_u32(const void* p) {
    return (uint32_t)__cvta_generic_to_shared(p);
}

__device__ __forceinline__ void cp16(uint32_t dst, const void* src) {
    asm volatile("cp.async.cg.shared.global [%0], [%1], 16;"
                 :: "r"(dst), "l"(src) : "memory");
}
#define CP_COMMIT() asm volatile("cp.async.commit_group;" ::: "memory")
#define CP_WAIT(n)  asm volatile("cp.async.wait_group %0;" :: "n"(n) : "memory")

// ---------------------------------------------------------------------------
// fp32 -> fp16 convert (8 elems/thread)
// ---------------------------------------------------------------------------
__global__ __launch_bounds__(256) void f2h(
    const float* __restrict__ in, __half* __restrict__ out, int n)
{
    int i = (blockIdx.x * 256 + threadIdx.x) * 8;
    if (i < n) {
        float4 a = *(const float4*)(in + i);
        float4 b = *(const float4*)(in + i + 4);
        uint4 t;
        t.x = h2(a.x, a.y); t.y = h2(a.z, a.w);
        t.z = h2(b.x, b.y); t.w = h2(b.z, b.w);
        *(uint4*)(out + i) = t;
    }
}

// ---------------------------------------------------------------------------
// FP16 tensor-core GEMM (NT): C[m][n] = sum_k A[m][k]*B[n][k] + bias[n]
// CTA tile 128(M) x 256(N), BK=32, 8 warps (2m x 4n), warp tile 64x64.
// Per k16 step: 8 LDSM -> 32 independent MMAs (deep per-warp ILP; 1 CTA/SM).
// 4-stage cp.async ring. Rows of 32 halves, stride 20 words (LDSM clean).
// ---------------------------------------------------------------------------
#define GS 20
#define AW (128 * GS)                 // A words per stage (2560)
#define BW (256 * GS)                 // B words per stage (5120)
#define STG_W (AW + BW)               // 7680 words per stage
#define GEMM_SMEM_B (4 * STG_W * 4)   // 122880 bytes

template<bool OUTH>
__global__ __launch_bounds__(256) void gemm_f16(
    const __half* __restrict__ A, const __half* __restrict__ B,
    const float* __restrict__ bias, void* __restrict__ Cout,
    int M, int N, int K)
{
    extern __shared__ uint32_t gsm[];
    const uint32_t smb = smem_u32(gsm);

    const int tid  = threadIdx.x;
    const int warp = tid >> 5;
    const int lane = tid & 31;
    const int gid  = lane >> 2;
    const int tig  = lane & 3;
    const int wm   = warp >> 2;   // 0..1  (M)
    const int wn   = warp & 3;    // 0..3  (N)
    const int bm   = blockIdx.y * 128;
    const int bn   = blockIdx.x * 256;

    // loader: 1536 16B-chunks per stage (A: 512, B: 1024); 6 per thread
    uint32_t sdst[6];
    const __half* gsrc[6];
#pragma unroll
    for (int i = 0; i < 6; i++) {
        int ch = tid + 256 * i;
        if (ch < 512) {
            int row = ch >> 2, j = ch & 3;
            sdst[i] = (uint32_t)((row * GS + j * 4) * 4);
            gsrc[i] = A + (size_t)(bm + row) * K + j * 8;
        } else {
            int c2 = ch - 512;
            int row = c2 >> 2, j = c2 & 3;
            sdst[i] = (uint32_t)((AW + row * GS + j * 4) * 4);
            gsrc[i] = B + (size_t)(bn + row) * K + j * 8;
        }
    }

#define GLOAD(c, s) do {                                                     \
    uint32_t base = smb + (uint32_t)((s) * STG_W) * 4;                       \
    size_t ko = (size_t)(c) * 32;                                            \
    _Pragma("unroll") for (int i = 0; i < 6; i++)                            \
        cp16(base + sdst[i], gsrc[i] + ko);                                  \
    CP_COMMIT(); } while (0)

    // ldmatrix lane mapping
    const int rowoff = ((lane >> 3) & 1) * 8 + (lane & 7);
    const int kxw    = (lane >> 4) * 4;

    uint32_t aBase[4], bBase[4];
#pragma unroll
    for (int mt = 0; mt < 4; mt++)
        aBase[mt] = (uint32_t)(((wm * 64 + mt * 16 + rowoff) * GS + kxw) * 4);
#pragma unroll
    for (int np = 0; np < 4; np++)
        bBase[np] = (uint32_t)((AW + (wn * 64 + np * 16 + rowoff) * GS + kxw) * 4);

    float acc[4][8][4];
#pragma unroll
    for (int i = 0; i < 4; i++)
#pragma unroll
        for (int j = 0; j < 8; j++)
#pragma unroll
            for (int e = 0; e < 4; e++) acc[i][j][e] = 0.f;

    const int nch = K >> 5;   // 32
    GLOAD(0, 0);
    GLOAD(1, 1);
    GLOAD(2, 2);

    for (int c = 0; c < nch; c++) {
        const int rem = nch - 1 - c;          // groups committed after c
        if (rem >= 2)      CP_WAIT(2);
        else if (rem == 1) CP_WAIT(1);
        else               CP_WAIT(0);
        __syncthreads();   // stage c ready; all warps done with stage (c+3)%4
        if (c + 3 < nch) GLOAD(c + 3, (c + 3) & 3);

        const uint32_t sb = smb + (uint32_t)((c & 3) * STG_W) * 4;
#pragma unroll
        for (int ks = 0; ks < 2; ks++) {
            uint32_t af[4][4], bq[4][4];
#pragma unroll
            for (int mt = 0; mt < 4; mt++)
                ldsm4(af[mt], sb + aBase[mt] + ks * 32);
#pragma unroll
            for (int np = 0; np < 4; np++)
                ldsm4(bq[np], sb + bBase[np] + ks * 32);
            // bq[np]: M0=(nLo,kLo) M1=(nHi,kLo) M2=(nLo,kHi) M3=(nHi,kHi)
#pragma unroll
            for (int mt = 0; mt < 4; mt++)
#pragma unroll
                for (int np = 0; np < 4; np++) {
                    mmah(acc[mt][2 * np],     af[mt], bq[np][0], bq[np][2]);
                    mmah(acc[mt][2 * np + 1], af[mt], bq[np][1], bq[np][3]);
                }
        }
    }
#undef GLOAD

    // epilogue
#pragma unroll
    for (int mt = 0; mt < 4; mt++) {
        int r0 = bm + wm * 64 + mt * 16 + gid;
#pragma unroll
        for (int nt = 0; nt < 8; nt++) {
            int c = bn + wn * 64 + nt * 8 + tig * 2;
            float2 b2 = *(const float2*)&bias[c];
            float vx0 = acc[mt][nt][0] + b2.x, vy0 = acc[mt][nt][1] + b2.y;
            float vx1 = acc[mt][nt][2] + b2.x, vy1 = acc[mt][nt][3] + b2.y;
            if (OUTH) {
                __half* Ch = (__half*)Cout;
                *(uint32_t*)&Ch[(size_t)r0 * N + c]       = h2(vx0, vy0);
                *(uint32_t*)&Ch[(size_t)(r0 + 8) * N + c] = h2(vx1, vy1);
            } else {
                float* Cf = (float*)Cout;
                *(float2*)&Cf[(size_t)r0 * N + c]       = make_float2(vx0, vy0);
                *(float2*)&Cf[(size_t)(r0 + 8) * N + c] = make_float2(vx1, vy1);
            }
        }
    }
}

// ---------------------------------------------------------------------------
// FP16 flash attention (causal), fp16 qkv in / fp16 y out.  (R10/R11, proven)
// ---------------------------------------------------------------------------
#define FS3 36
#define PS_W (128 * FS3)           // 4608 words
#define KV_W (64 * FS3)            // 2304 words
#define FL_SMEM_B ((PS_W + 4 * KV_W) * 4)   // 55296 bytes

__global__ __launch_bounds__(256) void flash_attn_f16(
    const __half* __restrict__ qkv, __half* __restrict__ y)
{
    extern __shared__ uint32_t sm[];
    uint32_t* Ps = sm;   // [q=128][64 halves] (Q staging, then P)

    const int tid  = threadIdx.x;
    const int warp = tid >> 5;
    const int lane = tid & 31;
    const int gid  = lane >> 2;
    const int tig  = lane & 3;

    const int rowoff = ((lane >> 3) & 1) * 8 + (lane & 7);
    const int kxw    = (lane >> 4) * 4;

    const uint32_t smb  = smem_u32(sm);
    const uint32_t kvb0 = smb + (uint32_t)PS_W * 4;

    const int qblk = (gridDim.x - 1) - blockIdx.x;   // big blocks first
    const int b    = blockIdx.y >> 4;
    const int h    = blockIdx.y & 15;

    const __half* base  = qkv + (size_t)b * TSEQ * C3 + h * DK;
    const int m0g = qblk * 128;
    const __half* baseQ = base + (size_t)m0g * C3;
    const __half* baseK = base + D_MODEL;
    const __half* baseV = base + 2 * D_MODEL;

    const int fr0 = tid >> 3;    // 0..31
    const int fj  = tid & 7;
    const uint32_t kv_d0 = (fr0 * FS3 + fj * 4) * 4;
    const uint32_t kv_d1 = ((fr0 + 32) * FS3 + fj * 4) * 4;

#define KVLOAD(kb, buf) do {                                                  \
    uint32_t kd = kvb0 + (uint32_t)((buf) * 2 * KV_W) * 4;                    \
    uint32_t vd = kd + (uint32_t)KV_W * 4;                                    \
    size_t ko = (size_t)((kb) * 64) * C3;                                     \
    cp16(kd + kv_d0, baseK + ko + (size_t)fr0 * C3 + fj * 8);                 \
    cp16(kd + kv_d1, baseK + ko + (size_t)(fr0 + 32) * C3 + fj * 8);          \
    cp16(vd + kv_d0, baseV + ko + (size_t)fr0 * C3 + fj * 8);                 \
    cp16(vd + kv_d1, baseV + ko + (size_t)(fr0 + 32) * C3 + fj * 8);          \
    CP_COMMIT(); } while (0)

#pragma unroll
    for (int i = 0; i < 4; i++) {
        int row = fr0 + 32 * i;
        cp16(smb + (uint32_t)((row * FS3 + fj * 4) * 4),
             baseQ + (size_t)row * C3 + fj * 8);
    }
    KVLOAD(0, 0);
    CP_WAIT(0);
    __syncthreads();

    uint32_t pAddr[4];
#pragma unroll
    for (int kt = 0; kt < 4; kt++)
        pAddr[kt] = smb + 4 * ((warp * 16 + rowoff) * FS3 + kt * 8 + kxw);

    uint32_t qf[4][4];
#pragma unroll
    for (int kt = 0; kt < 4; kt++) ldsm4(qf[kt], pAddr[kt]);

    float o[8][4];
#pragma unroll
    for (int nt = 0; nt < 8; nt++)
#pragma unroll
        for (int e = 0; e < 4; e++) o[nt][e] = 0.f;
    float mx0 = -1e30f, mx1 = -1e30f, l0 = 0.f, l1 = 0.f;

    const int rglob0 = m0g + warp * 16 + gid;
    const int rglob1 = rglob0 + 8;
    const int nkb = 2 * qblk + 2;

    for (int kb = 0; kb < nkb; kb++) {
        const int s = kb & 1;
        if (kb > 0) CP_WAIT(0);
        __syncthreads();
        if (kb + 1 < nkb) KVLOAD(kb + 1, 1 - s);

        const uint32_t Ks_b = kvb0 + (uint32_t)(s * 2 * KV_W) * 4;
        const uint32_t Vs_b = Ks_b + (uint32_t)KV_W * 4;

        float sc[8][4];
#pragma unroll
        for (int nt = 0; nt < 8; nt++)
#pragma unroll
            for (int e = 0; e < 4; e++) sc[nt][e] = 0.f;

#pragma unroll
        for (int kt = 0; kt < 4; kt++) {
#pragma unroll
            for (int ntp = 0; ntp < 4; ntp++) {
                uint32_t bq[4];
                ldsm4(bq, Ks_b + 4 * ((ntp * 16 + rowoff) * FS3 + kt * 8 + kxw));
                mmah(sc[2 * ntp],     qf[kt], bq[0], bq[2]);
                mmah(sc[2 * ntp + 1], qf[kt], bq[1], bq[3]);
            }
        }

        const float scale = 0.125f;
        if (kb >= 2 * qblk) {
#pragma unroll
            for (int nt = 0; nt < 8; nt++) {
                int c0 = kb * 64 + nt * 8 + tig * 2;
                sc[nt][0] = (c0     > rglob0) ? -1e30f : sc[nt][0] * scale;
                sc[nt][1] = (c0 + 1 > rglob0) ? -1e30f : sc[nt][1] * scale;
                sc[nt][2] = (c0     > rglob1) ? -1e30f : sc[nt][2] * scale;
                sc[nt][3] = (c0 + 1 > rglob1) ? -1e30f : sc[nt][3] * scale;
            }
        } else {
#pragma unroll
            for (int nt = 0; nt < 8; nt++)
#pragma unroll
                for (int e = 0; e < 4; e++) sc[nt][e] *= scale;
        }

        float vm0 = -1e30f, vm1 = -1e30f;
#pragma unroll
        for (int nt = 0; nt < 8; nt++) {
            vm0 = fmaxf(vm0, fmaxf(sc[nt][0], sc[nt][1]));
            vm1 = fmaxf(vm1, fmaxf(sc[nt][2], sc[nt][3]));
        }
        vm0 = fmaxf(vm0, __shfl_xor_sync(0xffffffffu, vm0, 1));
        vm0 = fmaxf(vm0, __shfl_xor_sync(0xffffffffu, vm0, 2));
        vm1 = fmaxf(vm1, __shfl_xor_sync(0xffffffffu, vm1, 1));
        vm1 = fmaxf(vm1, __shfl_xor_sync(0xffffffffu, vm1, 2));

        float nm0 = fmaxf(mx0, vm0), nm1 = fmaxf(mx1, vm1);
        float al0 = __expf(mx0 - nm0), al1 = __expf(mx1 - nm1);

        float sum0 = 0.f, sum1 = 0.f;
#pragma unroll
        for (int nt = 0; nt < 8; nt++) {
            sc[nt][0] = __expf(sc[nt][0] - nm0);
            sc[nt][1] = __expf(sc[nt][1] - nm0);
            sc[nt][2] = __expf(sc[nt][2] - nm1);
            sc[nt][3] = __expf(sc[nt][3] - nm1);
            sum0 += sc[nt][0] + sc[nt][1];
            sum1 += sc[nt][2] + sc[nt][3];
        }
        sum0 += __shfl_xor_sync(0xffffffffu, sum0, 1);
        sum0 += __shfl_xor_sync(0xffffffffu, sum0, 2);
        sum1 += __shfl_xor_sync(0xffffffffu, sum1, 1);
        sum1 += __shfl_xor_sync(0xffffffffu, sum1, 2);

        l0 = l0 * al0 + sum0;  mx0 = nm0;
        l1 = l1 * al1 + sum1;  mx1 = nm1;

#pragma unroll
        for (int nt = 0; nt < 8; nt++) {
            o[nt][0] *= al0; o[nt][1] *= al0;
            o[nt][2] *= al1; o[nt][3] *= al1;
        }

        {
            const int rl0 = warp * 16 + gid;
#pragma unroll
            for (int nt = 0; nt < 8; nt++) {
                Ps[rl0 * FS3 + nt * 4 + tig]       = h2(sc[nt][0], sc[nt][1]);
                Ps[(rl0 + 8) * FS3 + nt * 4 + tig] = h2(sc[nt][2], sc[nt][3]);
            }
        }
        __syncwarp();

#pragma unroll
        for (int kt = 0; kt < 4; kt++) {
            uint32_t af[4];
            ldsm4(af, pAddr[kt]);
#pragma unroll
            for (int ntp = 0; ntp < 4; ntp++) {
                uint32_t bq[4];
                ldsm4t(bq, Vs_b + 4 * ((kt * 16 + rowoff) * FS3 + ntp * 8 + kxw));
                mmah(o[2 * ntp],     af, bq[0], bq[1]);
                mmah(o[2 * ntp + 1], af, bq[2], bq[3]);
            }
        }
    }
#undef KVLOAD

    const float inv0 = 1.f / l0, inv1 = 1.f / l1;
    const int yrow0 = b * TSEQ + m0g + warp * 16 + gid;
#pragma unroll
    for (int nt = 0; nt < 8; nt++) {
        int c = h * DK + nt * 8 + tig * 2;
        *(uint32_t*)&y[(size_t)yrow0 * D_MODEL + c] =
            h2(o[nt][0] * inv0, o[nt][1] * inv0);
        *(uint32_t*)&y[(size_t)(yrow0 + 8) * D_MODEL + c] =
            h2(o[nt][2] * inv1, o[nt][3] * inv1);
    }
}

// ---------------------------------------------------------------------------
// launch
// ---------------------------------------------------------------------------
extern "C" void kernel_launch(void* const* d_in, const int* in_sizes, int n_in,
                              void* d_out, int out_size)
{
    const float* x      = (const float*)d_in[0];
    const float* W_attn = (const float*)d_in[1];
    const float* b_attn = (const float*)d_in[2];
    const float* W_o    = (const float*)d_in[3];
    const float* b_o    = (const float*)d_in[4];
    float* out = (float*)d_out;

    __half *hx, *hw, *hwo, *hqkv, *hy;
    cudaGetSymbolAddress((void**)&hx,   g_hx);
    cudaGetSymbolAddress((void**)&hw,   g_hw);
    cudaGetSymbolAddress((void**)&hwo,  g_hwo);
    cudaGetSymbolAddress((void**)&hqkv, g_qkv);
    cudaGetSymbolAddress((void**)&hy,   g_hy);

    // 0) one-time fp32 -> fp16 converts
    f2h<<<(BT * D_MODEL) / 2048, 256>>>(x, hx, BT * D_MODEL);
    f2h<<<(C3 * D_MODEL) / 2048, 256>>>(W_attn, hw, C3 * D_MODEL);
    f2h<<<(D_MODEL * D_MODEL) / 2048, 256>>>(W_o, hwo, D_MODEL * D_MODEL);

    cudaFuncSetAttribute(gemm_f16<true>,
                         cudaFuncAttributeMaxDynamicSharedMemorySize, GEMM_SMEM_B);
    cudaFuncSetAttribute(gemm_f16<false>,
                         cudaFuncAttributeMaxDynamicSharedMemorySize, GEMM_SMEM_B);
    cudaFuncSetAttribute(flash_attn_f16,
                         cudaFuncAttributeMaxDynamicSharedMemorySize, FL_SMEM_B);

    // 1) QKV projection: [8192,1024] @ [3072,1024]^T + b -> fp16 [8192,3072]
    gemm_f16<true><<<dim3(C3 / 256, BT / 128), 256, GEMM_SMEM_B>>>(
        hx, hw, b_attn, hqkv, BT, C3, D_MODEL);

    // 2) causal flash attention -> fp16 y [8192,1024]
    flash_attn_f16<<<dim3(TSEQ / 128, BATCH * NH), 256, FL_SMEM_B>>>(hqkv, hy);

    // 3) output projection: [8192,1024] @ [1024,1024]^T + b -> fp32 out
    gemm_f16<false><<<dim3(D_MODEL / 256, BT / 128), 256, GEMM_SMEM_B>>>(
        hy, hwo, b_o, out, BT, D_MODEL, D_MODEL);
}

// round 13
// speedup vs baseline: 1.0698x; 1.0698x over previous
#include <cuda_runtime.h>
#include <cuda_fp16.h>
#include <math.h>
#include <stdint.h>

// Problem constants
#define D_MODEL 1024
#define NH      16
#define DK      64
#define BATCH   4
#define TSEQ    2048
#define BT      (BATCH * TSEQ)      // 8192 rows
#define C3      (3 * D_MODEL)       // 3072

// Scratch (allocation-free rule: __device__ globals), all fp16
__device__ __half g_hx[BT * D_MODEL];        // 16 MB  x
__device__ __half g_hw[C3 * D_MODEL];        //  6 MB  W_attn
__device__ __half g_hwo[D_MODEL * D_MODEL];  //  2 MB  W_o
__device__ __half g_qkv[BT * C3];            // 48 MB  QKV
__device__ __half g_hy[BT * D_MODEL];        // 16 MB  attention out

// ---------------------------------------------------------------------------
// helpers
// ---------------------------------------------------------------------------
__device__ __forceinline__ uint32_t h2(float lo, float hi) {
    uint32_t r;
    asm("cvt.rn.f16x2.f32 %0, %1, %2;" : "=r"(r) : "f"(hi), "f"(lo));
    return r;
}

__device__ __forceinline__ void mmah(float c[4], const uint32_t a[4],
                                     uint32_t b0, uint32_t b1) {
    asm volatile(
        "mma.sync.aligned.m16n8k16.row.col.f32.f16.f16.f32 "
        "{%0,%1,%2,%3},{%4,%5,%6,%7},{%8,%9},{%0,%1,%2,%3};"
        : "+f"(c[0]), "+f"(c[1]), "+f"(c[2]), "+f"(c[3])
        : "r"(a[0]), "r"(a[1]), "r"(a[2]), "r"(a[3]), "r"(b0), "r"(b1));
}

__device__ __forceinline__ void ldsm4(uint32_t f[4], uint32_t addr) {
    asm volatile("ldmatrix.sync.aligned.m8n8.x4.shared.b16 {%0,%1,%2,%3}, [%4];"
        : "=r"(f[0]), "=r"(f[1]), "=r"(f[2]), "=r"(f[3]) : "r"(addr));
}

__device__ __forceinline__ void ldsm4t(uint32_t f[4], uint32_t addr) {
    asm volatile("ldmatrix.sync.aligned.m8n8.x4.trans.shared.b16 {%0,%1,%2,%3}, [%4];"
        : "=r"(f[0]), "=r"(f[1]), "=r"(f[2]), "=r"(f[3]) : "r"(addr));
}

__device__ __forceinline__ uint32_t smem_u32(const void* p) {
    return (uint32_t)__cvta_generic_to_shared(p);
}

__device__ __forceinline__ void cp16(uint32_t dst, const void* src) {
    asm volatile("cp.async.cg.shared.global [%0], [%1], 16;"
                 :: "r"(dst), "l"(src) : "memory");
}
#define CP_COMMIT() asm volatile("cp.async.commit_group;" ::: "memory")
#define CP_WAIT(n)  asm volatile("cp.async.wait_group %0;" :: "n"(n) : "memory")

// ---------------------------------------------------------------------------
// fp32 -> fp16 convert (8 elems/thread)
// ---------------------------------------------------------------------------
__global__ __launch_bounds__(256) void f2h(
    const float* __restrict__ in, __half* __restrict__ out, int n)
{
    int i = (blockIdx.x * 256 + threadIdx.x) * 8;
    if (i < n) {
        float4 a = *(const float4*)(in + i);
        float4 b = *(const float4*)(in + i + 4);
        uint4 t;
        t.x = h2(a.x, a.y); t.y = h2(a.z, a.w);
        t.z = h2(b.x, b.y); t.w = h2(b.z, b.w);
        *(uint4*)(out + i) = t;
    }
}

// ---------------------------------------------------------------------------
// FP16 tensor-core GEMM (NT): C[m][n] = sum_k A[m][k]*B[n][k] + bias[n]
// CTA 128x128, 512 threads = 16 warps (4m x 4n), warp tile 32x32, BK=64.
// 3-stage cp.async ring (prefetch distance 2, one barrier per chunk).
// Fragments double-buffered across ks: LDSM(ks+1) overlaps MMAs(ks).
// Rows of 64 halves, stride 36 words (9r mod 8 -> LDSM conflict-free).
// ---------------------------------------------------------------------------
#define GS2 36
#define GMW2 (128 * GS2)              // words per matrix per stage (4608)
#define GSTG2 (2 * GMW2)              // words per stage (A+B) = 9216
#define GEMM_SMEM_B (3 * GSTG2 * 4)   // 110592 bytes

template<bool OUTH>
__global__ __launch_bounds__(512, 1) void gemm_f16(
    const __half* __restrict__ A, const __half* __restrict__ B,
    const float* __restrict__ bias, void* __restrict__ Cout,
    int M, int N, int K)
{
    extern __shared__ uint32_t gsm[];
    const uint32_t smb = smem_u32(gsm);

    const int tid  = threadIdx.x;
    const int warp = tid >> 5;
    const int lane = tid & 31;
    const int gid  = lane >> 2;
    const int tig  = lane & 3;
    const int wm   = warp >> 2;   // 0..3  (M)
    const int wn   = warp & 3;    // 0..3  (N)
    const int bm   = blockIdx.y * 128;
    const int bn   = blockIdx.x * 128;

    // loader: per stage A,B each 128 rows x 8 x 16B chunks (1024 chunks);
    // 512 threads -> 2 chunks per matrix per thread (rows r, r+64)
    const int lr = tid >> 3;            // 0..63
    const int lj = tid & 7;             // chunk in row
    const __half* Ag0 = A + (size_t)(bm + lr) * K + lj * 8;
    const __half* Ag1 = A + (size_t)(bm + lr + 64) * K + lj * 8;
    const __half* Bg0 = B + (size_t)(bn + lr) * K + lj * 8;
    const __half* Bg1 = B + (size_t)(bn + lr + 64) * K + lj * 8;
    const uint32_t da0 = (uint32_t)((lr * GS2 + lj * 4) * 4);
    const uint32_t da1 = (uint32_t)(((lr + 64) * GS2 + lj * 4) * 4);
    const uint32_t db0 = (uint32_t)(GMW2 * 4) + da0;
    const uint32_t db1 = (uint32_t)(GMW2 * 4) + da1;

#define GLOAD(c, s) do {                                                     \
    uint32_t base = smb + (uint32_t)((s) * GSTG2) * 4;                       \
    size_t ko = (size_t)(c) * 64;                                            \
    cp16(base + da0, Ag0 + ko); cp16(base + da1, Ag1 + ko);                  \
    cp16(base + db0, Bg0 + ko); cp16(base + db1, Bg1 + ko);                  \
    CP_COMMIT(); } while (0)

    // ldmatrix lane mapping
    const int rowoff = ((lane >> 3) & 1) * 8 + (lane & 7);
    const int kxw    = (lane >> 4) * 4;

    uint32_t aBase[2], bBase[2];
#pragma unroll
    for (int mt = 0; mt < 2; mt++)
        aBase[mt] = (uint32_t)(((wm * 32 + mt * 16 + rowoff) * GS2 + kxw) * 4);
#pragma unroll
    for (int np = 0; np < 2; np++)
        bBase[np] = (uint32_t)((GMW2 + (wn * 32 + np * 16 + rowoff) * GS2 + kxw) * 4);

    float acc[2][4][4];
#pragma unroll
    for (int i = 0; i < 2; i++)
#pragma unroll
        for (int j = 0; j < 4; j++)
#pragma unroll
            for (int e = 0; e < 4; e++) acc[i][j][e] = 0.f;

    const int nch = K >> 6;   // 16
    GLOAD(0, 0);
    GLOAD(1, 1);

    uint32_t af[2][2][4], bq[2][2][4];   // [buf][tile][frag]

    for (int c = 0; c < nch; c++) {
        if (c + 1 < nch) CP_WAIT(1);
        else             CP_WAIT(0);
        __syncthreads();   // stage c ready; all warps done with stage (c+2)%3
        if (c + 2 < nch) GLOAD(c + 2, (c + 2) % 3);

        const uint32_t sb = smb + (uint32_t)((c % 3) * GSTG2) * 4;

        // fill buffer 0 (ks = 0)
        ldsm4(af[0][0], sb + aBase[0]);
        ldsm4(af[0][1], sb + aBase[1]);
        ldsm4(bq[0][0], sb + bBase[0]);
        ldsm4(bq[0][1], sb + bBase[1]);

#pragma unroll
        for (int ks = 0; ks < 4; ks++) {
            const int cur = ks & 1, nxt = cur ^ 1;
            if (ks < 3) {   // prefetch ks+1 fragments during MMAs
                const uint32_t o = (uint32_t)((ks + 1) * 32);
                ldsm4(af[nxt][0], sb + aBase[0] + o);
                ldsm4(af[nxt][1], sb + aBase[1] + o);
                ldsm4(bq[nxt][0], sb + bBase[0] + o);
                ldsm4(bq[nxt][1], sb + bBase[1] + o);
            }
#pragma unroll
            for (int mt = 0; mt < 2; mt++)
#pragma unroll
                for (int np = 0; np < 2; np++) {
                    mmah(acc[mt][2 * np],     af[cur][mt], bq[cur][np][0], bq[cur][np][2]);
                    mmah(acc[mt][2 * np + 1], af[cur][mt], bq[cur][np][1], bq[cur][np][3]);
                }
        }
    }
#undef GLOAD

    // epilogue
#pragma unroll
    for (int mt = 0; mt < 2; mt++) {
        int r0 = bm + wm * 32 + mt * 16 + gid;
#pragma unroll
        for (int nt = 0; nt < 4; nt++) {
            int c = bn + wn * 32 + nt * 8 + tig * 2;
            float2 b2 = *(const float2*)&bias[c];
            float vx0 = acc[mt][nt][0] + b2.x, vy0 = acc[mt][nt][1] + b2.y;
            float vx1 = acc[mt][nt][2] + b2.x, vy1 = acc[mt][nt][3] + b2.y;
            if (OUTH) {
                __half* Ch = (__half*)Cout;
                *(uint32_t*)&Ch[(size_t)r0 * N + c]       = h2(vx0, vy0);
                *(uint32_t*)&Ch[(size_t)(r0 + 8) * N + c] = h2(vx1, vy1);
            } else {
                float* Cf = (float*)Cout;
                *(float2*)&Cf[(size_t)r0 * N + c]       = make_float2(vx0, vy0);
                *(float2*)&Cf[(size_t)(r0 + 8) * N + c] = make_float2(vx1, vy1);
            }
        }
    }
}

// ---------------------------------------------------------------------------
// FP16 flash attention (causal), fp16 qkv in / fp16 y out.  (R10/R11, proven)
// ---------------------------------------------------------------------------
#define FS3 36
#define PS_W (128 * FS3)           // 4608 words
#define KV_W (64 * FS3)            // 2304 words
#define FL_SMEM_B ((PS_W + 4 * KV_W) * 4)   // 55296 bytes

__global__ __launch_bounds__(256) void flash_attn_f16(
    const __half* __restrict__ qkv, __half* __restrict__ y)
{
    extern __shared__ uint32_t sm[];
    uint32_t* Ps = sm;   // [q=128][64 halves] (Q staging, then P)

    const int tid  = threadIdx.x;
    const int warp = tid >> 5;
    const int lane = tid & 31;
    const int gid  = lane >> 2;
    const int tig  = lane & 3;

    const int rowoff = ((lane >> 3) & 1) * 8 + (lane & 7);
    const int kxw    = (lane >> 4) * 4;

    const uint32_t smb  = smem_u32(sm);
    const uint32_t kvb0 = smb + (uint32_t)PS_W * 4;

    const int qblk = (gridDim.x - 1) - blockIdx.x;   // big blocks first
    const int b    = blockIdx.y >> 4;
    const int h    = blockIdx.y & 15;

    const __half* base  = qkv + (size_t)b * TSEQ * C3 + h * DK;
    const int m0g = qblk * 128;
    const __half* baseQ = base + (size_t)m0g * C3;
    const __half* baseK = base + D_MODEL;
    const __half* baseV = base + 2 * D_MODEL;

    const int fr0 = tid >> 3;    // 0..31
    const int fj  = tid & 7;
    const uint32_t kv_d0 = (fr0 * FS3 + fj * 4) * 4;
    const uint32_t kv_d1 = ((fr0 + 32) * FS3 + fj * 4) * 4;

#define KVLOAD(kb, buf) do {                                                  \
    uint32_t kd = kvb0 + (uint32_t)((buf) * 2 * KV_W) * 4;                    \
    uint32_t vd = kd + (uint32_t)KV_W * 4;                                    \
    size_t ko = (size_t)((kb) * 64) * C3;                                     \
    cp16(kd + kv_d0, baseK + ko + (size_t)fr0 * C3 + fj * 8);                 \
    cp16(kd + kv_d1, baseK + ko + (size_t)(fr0 + 32) * C3 + fj * 8);          \
    cp16(vd + kv_d0, baseV + ko + (size_t)fr0 * C3 + fj * 8);                 \
    cp16(vd + kv_d1, baseV + ko + (size_t)(fr0 + 32) * C3 + fj * 8);          \
    CP_COMMIT(); } while (0)

#pragma unroll
    for (int i = 0; i < 4; i++) {
        int row = fr0 + 32 * i;
        cp16(smb + (uint32_t)((row * FS3 + fj * 4) * 4),
             baseQ + (size_t)row * C3 + fj * 8);
    }
    KVLOAD(0, 0);
    CP_WAIT(0);
    __syncthreads();

    uint32_t pAddr[4];
#pragma unroll
    for (int kt = 0; kt < 4; kt++)
        pAddr[kt] = smb + 4 * ((warp * 16 + rowoff) * FS3 + kt * 8 + kxw);

    uint32_t qf[4][4];
#pragma unroll
    for (int kt = 0; kt < 4; kt++) ldsm4(qf[kt], pAddr[kt]);

    float o[8][4];
#pragma unroll
    for (int nt = 0; nt < 8; nt++)
#pragma unroll
        for (int e = 0; e < 4; e++) o[nt][e] = 0.f;
    float mx0 = -1e30f, mx1 = -1e30f, l0 = 0.f, l1 = 0.f;

    const int rglob0 = m0g + warp * 16 + gid;
    const int rglob1 = rglob0 + 8;
    const int nkb = 2 * qblk + 2;

    for (int kb = 0; kb < nkb; kb++) {
        const int s = kb & 1;
        if (kb > 0) CP_WAIT(0);
        __syncthreads();
        if (kb + 1 < nkb) KVLOAD(kb + 1, 1 - s);

        const uint32_t Ks_b = kvb0 + (uint32_t)(s * 2 * KV_W) * 4;
        const uint32_t Vs_b = Ks_b + (uint32_t)KV_W * 4;

        float sc[8][4];
#pragma unroll
        for (int nt = 0; nt < 8; nt++)
#pragma unroll
            for (int e = 0; e < 4; e++) sc[nt][e] = 0.f;

#pragma unroll
        for (int kt = 0; kt < 4; kt++) {
#pragma unroll
            for (int ntp = 0; ntp < 4; ntp++) {
                uint32_t bq[4];
                ldsm4(bq, Ks_b + 4 * ((ntp * 16 + rowoff) * FS3 + kt * 8 + kxw));
                mmah(sc[2 * ntp],     qf[kt], bq[0], bq[2]);
                mmah(sc[2 * ntp + 1], qf[kt], bq[1], bq[3]);
            }
        }

        const float scale = 0.125f;
        if (kb >= 2 * qblk) {
#pragma unroll
            for (int nt = 0; nt < 8; nt++) {
                int c0 = kb * 64 + nt * 8 + tig * 2;
                sc[nt][0] = (c0     > rglob0) ? -1e30f : sc[nt][0] * scale;
                sc[nt][1] = (c0 + 1 > rglob0) ? -1e30f : sc[nt][1] * scale;
                sc[nt][2] = (c0     > rglob1) ? -1e30f : sc[nt][2] * scale;
                sc[nt][3] = (c0 + 1 > rglob1) ? -1e30f : sc[nt][3] * scale;
            }
        } else {
#pragma unroll
            for (int nt = 0; nt < 8; nt++)
#pragma unroll
                for (int e = 0; e < 4; e++) sc[nt][e] *= scale;
        }

        float vm0 = -1e30f, vm1 = -1e30f;
#pragma unroll
        for (int nt = 0; nt < 8; nt++) {
            vm0 = fmaxf(vm0, fmaxf(sc[nt][0], sc[nt][1]));
            vm1 = fmaxf(vm1, fmaxf(sc[nt][2], sc[nt][3]));
        }
        vm0 = fmaxf(vm0, __shfl_xor_sync(0xffffffffu, vm0, 1));
        vm0 = fmaxf(vm0, __shfl_xor_sync(0xffffffffu, vm0, 2));
        vm1 = fmaxf(vm1, __shfl_xor_sync(0xffffffffu, vm1, 1));
        vm1 = fmaxf(vm1, __shfl_xor_sync(0xffffffffu, vm1, 2));

        float nm0 = fmaxf(mx0, vm0), nm1 = fmaxf(mx1, vm1);
        float al0 = __expf(mx0 - nm0), al1 = __expf(mx1 - nm1);

        float sum0 = 0.f, sum1 = 0.f;
#pragma unroll
        for (int nt = 0; nt < 8; nt++) {
            sc[nt][0] = __expf(sc[nt][0] - nm0);
            sc[nt][1] = __expf(sc[nt][1] - nm0);
            sc[nt][2] = __expf(sc[nt][2] - nm1);
            sc[nt][3] = __expf(sc[nt][3] - nm1);
            sum0 += sc[nt][0] + sc[nt][1];
            sum1 += sc[nt][2] + sc[nt][3];
        }
        sum0 += __shfl_xor_sync(0xffffffffu, sum0, 1);
        sum0 += __shfl_xor_sync(0xffffffffu, sum0, 2);
        sum1 += __shfl_xor_sync(0xffffffffu, sum1, 1);
        sum1 += __shfl_xor_sync(0xffffffffu, sum1, 2);

        l0 = l0 * al0 + sum0;  mx0 = nm0;
        l1 = l1 * al1 + sum1;  mx1 = nm1;

#pragma unroll
        for (int nt = 0; nt < 8; nt++) {
            o[nt][0] *= al0; o[nt][1] *= al0;
            o[nt][2] *= al1; o[nt][3] *= al1;
        }

        {
            const int rl0 = warp * 16 + gid;
#pragma unroll
            for (int nt = 0; nt < 8; nt++) {
                Ps[rl0 * FS3 + nt * 4 + tig]       = h2(sc[nt][0], sc[nt][1]);
                Ps[(rl0 + 8) * FS3 + nt * 4 + tig] = h2(sc[nt][2], sc[nt][3]);
            }
        }
        __syncwarp();

#pragma unroll
        for (int kt = 0; kt < 4; kt++) {
            uint32_t af[4];
            ldsm4(af, pAddr[kt]);
#pragma unroll
            for (int ntp = 0; ntp < 4; ntp++) {
                uint32_t bq[4];
                ldsm4t(bq, Vs_b + 4 * ((kt * 16 + rowoff) * FS3 + ntp * 8 + kxw));
                mmah(o[2 * ntp],     af, bq[0], bq[1]);
                mmah(o[2 * ntp + 1], af, bq[2], bq[3]);
            }
        }
    }
#undef KVLOAD

    const float inv0 = 1.f / l0, inv1 = 1.f / l1;
    const int yrow0 = b * TSEQ + m0g + warp * 16 + gid;
#pragma unroll
    for (int nt = 0; nt < 8; nt++) {
        int c = h * DK + nt * 8 + tig * 2;
        *(uint32_t*)&y[(size_t)yrow0 * D_MODEL + c] =
            h2(o[nt][0] * inv0, o[nt][1] * inv0);
        *(uint32_t*)&y[(size_t)(yrow0 + 8) * D_MODEL + c] =
            h2(o[nt][2] * inv1, o[nt][3] * inv1);
    }
}

// ---------------------------------------------------------------------------
// launch
// ---------------------------------------------------------------------------
extern "C" void kernel_launch(void* const* d_in, const int* in_sizes, int n_in,
                              void* d_out, int out_size)
{
    const float* x      = (const float*)d_in[0];
    const float* W_attn = (const float*)d_in[1];
    const float* b_attn = (const float*)d_in[2];
    const float* W_o    = (const float*)d_in[3];
    const float* b_o    = (const float*)d_in[4];
    float* out = (float*)d_out;

    __half *hx, *hw, *hwo, *hqkv, *hy;
    cudaGetSymbolAddress((void**)&hx,   g_hx);
    cudaGetSymbolAddress((void**)&hw,   g_hw);
    cudaGetSymbolAddress((void**)&hwo,  g_hwo);
    cudaGetSymbolAddress((void**)&hqkv, g_qkv);
    cudaGetSymbolAddress((void**)&hy,   g_hy);

    // 0) one-time fp32 -> fp16 converts
    f2h<<<(BT * D_MODEL) / 2048, 256>>>(x, hx, BT * D_MODEL);
    f2h<<<(C3 * D_MODEL) / 2048, 256>>>(W_attn, hw, C3 * D_MODEL);
    f2h<<<(D_MODEL * D_MODEL) / 2048, 256>>>(W_o, hwo, D_MODEL * D_MODEL);

    cudaFuncSetAttribute(gemm_f16<true>,
                         cudaFuncAttributeMaxDynamicSharedMemorySize, GEMM_SMEM_B);
    cudaFuncSetAttribute(gemm_f16<false>,
                         cudaFuncAttributeMaxDynamicSharedMemorySize, GEMM_SMEM_B);
    cudaFuncSetAttribute(flash_attn_f16,
                         cudaFuncAttributeMaxDynamicSharedMemorySize, FL_SMEM_B);

    // 1) QKV projection: [8192,1024] @ [3072,1024]^T + b -> fp16 [8192,3072]
    gemm_f16<true><<<dim3(C3 / 128, BT / 128), 512, GEMM_SMEM_B>>>(
        hx, hw, b_attn, hqkv, BT, C3, D_MODEL);

    // 2) causal flash attention -> fp16 y [8192,1024]
    flash_attn_f16<<<dim3(TSEQ / 128, BATCH * NH), 256, FL_SMEM_B>>>(hqkv, hy);

    // 3) output projection: [8192,1024] @ [1024,1024]^T + b -> fp32 out
    gemm_f16<false><<<dim3(D_MODEL / 128, BT / 128), 512, GEMM_SMEM_B>>>(
        hy, hwo, b_o, out, BT, D_MODEL, D_MODEL);
}

// round 14
// speedup vs baseline: 1.0921x; 1.0208x over previous
#include <cuda_runtime.h>
#include <cuda_fp16.h>
#include <math.h>
#include <stdint.h>

// Problem constants
#define D_MODEL 1024
#define NH      16
#define DK      64
#define BATCH   4
#define TSEQ    2048
#define BT      (BATCH * TSEQ)      // 8192 rows
#define C3      (3 * D_MODEL)       // 3072

// Scratch (allocation-free rule: __device__ globals), all fp16
__device__ __half g_hx[BT * D_MODEL];        // 16 MB  x
__device__ __half g_hw[C3 * D_MODEL];        //  6 MB  W_attn
__device__ __half g_hwo[D_MODEL * D_MODEL];  //  2 MB  W_o
__device__ __half g_qkv[BT * C3];            // 48 MB  QKV
__device__ __half g_hy[BT * D_MODEL];        // 16 MB  attention out

// ---------------------------------------------------------------------------
// helpers
// ---------------------------------------------------------------------------
__device__ __forceinline__ uint32_t h2(float lo, float hi) {
    uint32_t r;
    asm("cvt.rn.f16x2.f32 %0, %1, %2;" : "=r"(r) : "f"(hi), "f"(lo));
    return r;
}

// packed half2 2^x (one SFU op for two values)
__device__ __forceinline__ uint32_t ex2h2(uint32_t x) {
    uint32_t r;
    asm("ex2.approx.f16x2 %0, %1;" : "=r"(r) : "r"(x));
    return r;
}

__device__ __forceinline__ void mmah(float c[4], const uint32_t a[4],
                                     uint32_t b0, uint32_t b1) {
    asm volatile(
        "mma.sync.aligned.m16n8k16.row.col.f32.f16.f16.f32 "
        "{%0,%1,%2,%3},{%4,%5,%6,%7},{%8,%9},{%0,%1,%2,%3};"
        : "+f"(c[0]), "+f"(c[1]), "+f"(c[2]), "+f"(c[3])
        : "r"(a[0]), "r"(a[1]), "r"(a[2]), "r"(a[3]), "r"(b0), "r"(b1));
}

__device__ __forceinline__ void ldsm4(uint32_t f[4], uint32_t addr) {
    asm volatile("ldmatrix.sync.aligned.m8n8.x4.shared.b16 {%0,%1,%2,%3}, [%4];"
        : "=r"(f[0]), "=r"(f[1]), "=r"(f[2]), "=r"(f[3]) : "r"(addr));
}

__device__ __forceinline__ void ldsm4t(uint32_t f[4], uint32_t addr) {
    asm volatile("ldmatrix.sync.aligned.m8n8.x4.trans.shared.b16 {%0,%1,%2,%3}, [%4];"
        : "=r"(f[0]), "=r"(f[1]), "=r"(f[2]), "=r"(f[3]) : "r"(addr));
}

__device__ __forceinline__ uint32_t smem_u32(const void* p) {
    return (uint32_t)__cvta_generic_to_shared(p);
}

__device__ __forceinline__ void cp16(uint32_t dst, const void* src) {
    asm volatile("cp.async.cg.shared.global [%0], [%1], 16;"
                 :: "r"(dst), "l"(src) : "memory");
}
#define CP_COMMIT() asm volatile("cp.async.commit_group;" ::: "memory")
#define CP_WAIT(n)  asm volatile("cp.async.wait_group %0;" :: "n"(n) : "memory")

// ---------------------------------------------------------------------------
// fp32 -> fp16 convert (8 elems/thread)
// ---------------------------------------------------------------------------
__global__ __launch_bounds__(256) void f2h(
    const float* __restrict__ in, __half* __restrict__ out, int n)
{
    int i = (blockIdx.x * 256 + threadIdx.x) * 8;
    if (i < n) {
        float4 a = *(const float4*)(in + i);
        float4 b = *(const float4*)(in + i + 4);
        uint4 t;
        t.x = h2(a.x, a.y); t.y = h2(a.z, a.w);
        t.z = h2(b.x, b.y); t.w = h2(b.z, b.w);
        *(uint4*)(out + i) = t;
    }
}

// ---------------------------------------------------------------------------
// FP16 tensor-core GEMM (NT): C[m][n] = sum_k A[m][k]*B[n][k] + bias[n]
// CTA 128x128, 512 threads = 16 warps (4m x 4n), warp tile 32x32, BK=64.
// 3-stage cp.async ring; fragments double-buffered across ks.  (R13, proven)
// ---------------------------------------------------------------------------
#define GS2 36
#define GMW2 (128 * GS2)              // words per matrix per stage (4608)
#define GSTG2 (2 * GMW2)              // words per stage (A+B) = 9216
#define GEMM_SMEM_B (3 * GSTG2 * 4)   // 110592 bytes

template<bool OUTH>
__global__ __launch_bounds__(512, 1) void gemm_f16(
    const __half* __restrict__ A, const __half* __restrict__ B,
    const float* __restrict__ bias, void* __restrict__ Cout,
    int M, int N, int K)
{
    extern __shared__ uint32_t gsm[];
    const uint32_t smb = smem_u32(gsm);

    const int tid  = threadIdx.x;
    const int warp = tid >> 5;
    const int lane = tid & 31;
    const int gid  = lane >> 2;
    const int tig  = lane & 3;
    const int wm   = warp >> 2;   // 0..3  (M)
    const int wn   = warp & 3;    // 0..3  (N)
    const int bm   = blockIdx.y * 128;
    const int bn   = blockIdx.x * 128;

    const int lr = tid >> 3;            // 0..63
    const int lj = tid & 7;             // chunk in row
    const __half* Ag0 = A + (size_t)(bm + lr) * K + lj * 8;
    const __half* Ag1 = A + (size_t)(bm + lr + 64) * K + lj * 8;
    const __half* Bg0 = B + (size_t)(bn + lr) * K + lj * 8;
    const __half* Bg1 = B + (size_t)(bn + lr + 64) * K + lj * 8;
    const uint32_t da0 = (uint32_t)((lr * GS2 + lj * 4) * 4);
    const uint32_t da1 = (uint32_t)(((lr + 64) * GS2 + lj * 4) * 4);
    const uint32_t db0 = (uint32_t)(GMW2 * 4) + da0;
    const uint32_t db1 = (uint32_t)(GMW2 * 4) + da1;

#define GLOAD(c, s) do {                                                     \
    uint32_t base = smb + (uint32_t)((s) * GSTG2) * 4;                       \
    size_t ko = (size_t)(c) * 64;                                            \
    cp16(base + da0, Ag0 + ko); cp16(base + da1, Ag1 + ko);                  \
    cp16(base + db0, Bg0 + ko); cp16(base + db1, Bg1 + ko);                  \
    CP_COMMIT(); } while (0)

    const int rowoff = ((lane >> 3) & 1) * 8 + (lane & 7);
    const int kxw    = (lane >> 4) * 4;

    uint32_t aBase[2], bBase[2];
#pragma unroll
    for (int mt = 0; mt < 2; mt++)
        aBase[mt] = (uint32_t)(((wm * 32 + mt * 16 + rowoff) * GS2 + kxw) * 4);
#pragma unroll
    for (int np = 0; np < 2; np++)
        bBase[np] = (uint32_t)((GMW2 + (wn * 32 + np * 16 + rowoff) * GS2 + kxw) * 4);

    float acc[2][4][4];
#pragma unroll
    for (int i = 0; i < 2; i++)
#pragma unroll
        for (int j = 0; j < 4; j++)
#pragma unroll
            for (int e = 0; e < 4; e++) acc[i][j][e] = 0.f;

    const int nch = K >> 6;   // 16
    GLOAD(0, 0);
    GLOAD(1, 1);

    uint32_t af[2][2][4], bq[2][2][4];   // [buf][tile][frag]

    for (int c = 0; c < nch; c++) {
        if (c + 1 < nch) CP_WAIT(1);
        else             CP_WAIT(0);
        __syncthreads();   // stage c ready; all warps done with stage (c+2)%3
        if (c + 2 < nch) GLOAD(c + 2, (c + 2) % 3);

        const uint32_t sb = smb + (uint32_t)((c % 3) * GSTG2) * 4;

        ldsm4(af[0][0], sb + aBase[0]);
        ldsm4(af[0][1], sb + aBase[1]);
        ldsm4(bq[0][0], sb + bBase[0]);
        ldsm4(bq[0][1], sb + bBase[1]);

#pragma unroll
        for (int ks = 0; ks < 4; ks++) {
            const int cur = ks & 1, nxt = cur ^ 1;
            if (ks < 3) {
                const uint32_t o = (uint32_t)((ks + 1) * 32);
                ldsm4(af[nxt][0], sb + aBase[0] + o);
                ldsm4(af[nxt][1], sb + aBase[1] + o);
                ldsm4(bq[nxt][0], sb + bBase[0] + o);
                ldsm4(bq[nxt][1], sb + bBase[1] + o);
            }
#pragma unroll
            for (int mt = 0; mt < 2; mt++)
#pragma unroll
                for (int np = 0; np < 2; np++) {
                    mmah(acc[mt][2 * np],     af[cur][mt], bq[cur][np][0], bq[cur][np][2]);
                    mmah(acc[mt][2 * np + 1], af[cur][mt], bq[cur][np][1], bq[cur][np][3]);
                }
        }
    }
#undef GLOAD

    // epilogue
#pragma unroll
    for (int mt = 0; mt < 2; mt++) {
        int r0 = bm + wm * 32 + mt * 16 + gid;
#pragma unroll
        for (int nt = 0; nt < 4; nt++) {
            int c = bn + wn * 32 + nt * 8 + tig * 2;
            float2 b2 = *(const float2*)&bias[c];
            float vx0 = acc[mt][nt][0] + b2.x, vy0 = acc[mt][nt][1] + b2.y;
            float vx1 = acc[mt][nt][2] + b2.x, vy1 = acc[mt][nt][3] + b2.y;
            if (OUTH) {
                __half* Ch = (__half*)Cout;
                *(uint32_t*)&Ch[(size_t)r0 * N + c]       = h2(vx0, vy0);
                *(uint32_t*)&Ch[(size_t)(r0 + 8) * N + c] = h2(vx1, vy1);
            } else {
                float* Cf = (float*)Cout;
                *(float2*)&Cf[(size_t)r0 * N + c]       = make_float2(vx0, vy0);
                *(float2*)&Cf[(size_t)(r0 + 8) * N + c] = make_float2(vx1, vy1);
            }
        }
    }
}

// ---------------------------------------------------------------------------
// FP16 flash attention (causal). Softmax exp via ex2.approx.f16x2:
// MUFU per key block drops 34 -> 18 ops; P comes out pre-packed half2.
// ---------------------------------------------------------------------------
#define FS3 36
#define PS_W (128 * FS3)           // 4608 words
#define KV_W (64 * FS3)            // 2304 words
#define FL_SMEM_B ((PS_W + 4 * KV_W) * 4)   // 55296 bytes

__global__ __launch_bounds__(256) void flash_attn_f16(
    const __half* __restrict__ qkv, __half* __restrict__ y)
{
    extern __shared__ uint32_t sm[];
    uint32_t* Ps = sm;   // [q=128][64 halves] (Q staging, then P)

    const int tid  = threadIdx.x;
    const int warp = tid >> 5;
    const int lane = tid & 31;
    const int gid  = lane >> 2;
    const int tig  = lane & 3;

    const int rowoff = ((lane >> 3) & 1) * 8 + (lane & 7);
    const int kxw    = (lane >> 4) * 4;

    const uint32_t smb  = smem_u32(sm);
    const uint32_t kvb0 = smb + (uint32_t)PS_W * 4;

    const int qblk = (gridDim.x - 1) - blockIdx.x;   // big blocks first
    const int b    = blockIdx.y >> 4;
    const int h    = blockIdx.y & 15;

    const __half* base  = qkv + (size_t)b * TSEQ * C3 + h * DK;
    const int m0g = qblk * 128;
    const __half* baseQ = base + (size_t)m0g * C3;
    const __half* baseK = base + D_MODEL;
    const __half* baseV = base + 2 * D_MODEL;

    const int fr0 = tid >> 3;    // 0..31
    const int fj  = tid & 7;
    const uint32_t kv_d0 = (fr0 * FS3 + fj * 4) * 4;
    const uint32_t kv_d1 = ((fr0 + 32) * FS3 + fj * 4) * 4;

#define KVLOAD(kb, buf) do {                                                  \
    uint32_t kd = kvb0 + (uint32_t)((buf) * 2 * KV_W) * 4;                    \
    uint32_t vd = kd + (uint32_t)KV_W * 4;                                    \
    size_t ko = (size_t)((kb) * 64) * C3;                                     \
    cp16(kd + kv_d0, baseK + ko + (size_t)fr0 * C3 + fj * 8);                 \
    cp16(kd + kv_d1, baseK + ko + (size_t)(fr0 + 32) * C3 + fj * 8);          \
    cp16(vd + kv_d0, baseV + ko + (size_t)fr0 * C3 + fj * 8);                 \
    cp16(vd + kv_d1, baseV + ko + (size_t)(fr0 + 32) * C3 + fj * 8);          \
    CP_COMMIT(); } while (0)

#pragma unroll
    for (int i = 0; i < 4; i++) {
        int row = fr0 + 32 * i;
        cp16(smb + (uint32_t)((row * FS3 + fj * 4) * 4),
             baseQ + (size_t)row * C3 + fj * 8);
    }
    KVLOAD(0, 0);
    CP_WAIT(0);
    __syncthreads();

    uint32_t pAddr[4];
#pragma unroll
    for (int kt = 0; kt < 4; kt++)
        pAddr[kt] = smb + 4 * ((warp * 16 + rowoff) * FS3 + kt * 8 + kxw);

    uint32_t qf[4][4];
#pragma unroll
    for (int kt = 0; kt < 4; kt++) ldsm4(qf[kt], pAddr[kt]);

    float o[8][4];
#pragma unroll
    for (int nt = 0; nt < 8; nt++)
#pragma unroll
        for (int e = 0; e < 4; e++) o[nt][e] = 0.f;
    float mx0 = -1e30f, mx1 = -1e30f, l0 = 0.f, l1 = 0.f;

    const int rglob0 = m0g + warp * 16 + gid;
    const int rglob1 = rglob0 + 8;
    const int nkb = 2 * qblk + 2;
    const float L2E = 1.4426950408889634f;   // log2(e)

    for (int kb = 0; kb < nkb; kb++) {
        const int s = kb & 1;
        if (kb > 0) CP_WAIT(0);
        __syncthreads();
        if (kb + 1 < nkb) KVLOAD(kb + 1, 1 - s);

        const uint32_t Ks_b = kvb0 + (uint32_t)(s * 2 * KV_W) * 4;
        const uint32_t Vs_b = Ks_b + (uint32_t)KV_W * 4;

        // ---- S = Q @ K^T
        float sc[8][4];
#pragma unroll
        for (int nt = 0; nt < 8; nt++)
#pragma unroll
            for (int e = 0; e < 4; e++) sc[nt][e] = 0.f;

#pragma unroll
        for (int kt = 0; kt < 4; kt++) {
#pragma unroll
            for (int ntp = 0; ntp < 4; ntp++) {
                uint32_t bq[4];
                ldsm4(bq, Ks_b + 4 * ((ntp * 16 + rowoff) * FS3 + kt * 8 + kxw));
                mmah(sc[2 * ntp],     qf[kt], bq[0], bq[2]);
                mmah(sc[2 * ntp + 1], qf[kt], bq[1], bq[3]);
            }
        }

        // ---- scale + causal mask
        const float scale = 0.125f;
        if (kb >= 2 * qblk) {
#pragma unroll
            for (int nt = 0; nt < 8; nt++) {
                int c0 = kb * 64 + nt * 8 + tig * 2;
                sc[nt][0] = (c0     > rglob0) ? -1e30f : sc[nt][0] * scale;
                sc[nt][1] = (c0 + 1 > rglob0) ? -1e30f : sc[nt][1] * scale;
                sc[nt][2] = (c0     > rglob1) ? -1e30f : sc[nt][2] * scale;
                sc[nt][3] = (c0 + 1 > rglob1) ? -1e30f : sc[nt][3] * scale;
            }
        } else {
#pragma unroll
            for (int nt = 0; nt < 8; nt++)
#pragma unroll
                for (int e = 0; e < 4; e++) sc[nt][e] *= scale;
        }

        // ---- online softmax (warp-local max/sum; exp via f16x2 EX2)
        float vm0 = -1e30f, vm1 = -1e30f;
#pragma unroll
        for (int nt = 0; nt < 8; nt++) {
            vm0 = fmaxf(vm0, fmaxf(sc[nt][0], sc[nt][1]));
            vm1 = fmaxf(vm1, fmaxf(sc[nt][2], sc[nt][3]));
        }
        vm0 = fmaxf(vm0, __shfl_xor_sync(0xffffffffu, vm0, 1));
        vm0 = fmaxf(vm0, __shfl_xor_sync(0xffffffffu, vm0, 2));
        vm1 = fmaxf(vm1, __shfl_xor_sync(0xffffffffu, vm1, 1));
        vm1 = fmaxf(vm1, __shfl_xor_sync(0xffffffffu, vm1, 2));

        float nm0 = fmaxf(mx0, vm0), nm1 = fmaxf(mx1, vm1);
        float al0 = __expf(mx0 - nm0), al1 = __expf(mx1 - nm1);

        // p = 2^((s - nm) * log2e), two at a time in f16x2
        const float nm0L = nm0 * L2E, nm1L = nm1 * L2E;
        uint32_t ph[8][2];     // packed half2 P: [nt][row0 / row1]
        float sum0 = 0.f, sum1 = 0.f;
#pragma unroll
        for (int nt = 0; nt < 8; nt++) {
            uint32_t a0 = h2(fmaf(sc[nt][0], L2E, -nm0L),
                             fmaf(sc[nt][1], L2E, -nm0L));
            uint32_t a1 = h2(fmaf(sc[nt][2], L2E, -nm1L),
                             fmaf(sc[nt][3], L2E, -nm1L));
            ph[nt][0] = ex2h2(a0);
            ph[nt][1] = ex2h2(a1);
            float2 p0 = __half22float2(*(__half2*)&ph[nt][0]);
            float2 p1 = __half22float2(*(__half2*)&ph[nt][1]);
            sum0 += p0.x + p0.y;
            sum1 += p1.x + p1.y;
        }
        sum0 += __shfl_xor_sync(0xffffffffu, sum0, 1);
        sum0 += __shfl_xor_sync(0xffffffffu, sum0, 2);
        sum1 += __shfl_xor_sync(0xffffffffu, sum1, 1);
        sum1 += __shfl_xor_sync(0xffffffffu, sum1, 2);

        l0 = l0 * al0 + sum0;  mx0 = nm0;
        l1 = l1 * al1 + sum1;  mx1 = nm1;

#pragma unroll
        for (int nt = 0; nt < 8; nt++) {
            o[nt][0] *= al0; o[nt][1] *= al0;
            o[nt][2] *= al1; o[nt][3] *= al1;
        }

        // ---- write P tile (already packed half2; warp-private rows)
        {
            const int rl0 = warp * 16 + gid;
#pragma unroll
            for (int nt = 0; nt < 8; nt++) {
                Ps[rl0 * FS3 + nt * 4 + tig]       = ph[nt][0];
                Ps[(rl0 + 8) * FS3 + nt * 4 + tig] = ph[nt][1];
            }
        }
        __syncwarp();

        // ---- O += P @ V (V via trans-LDSM)
#pragma unroll
        for (int kt = 0; kt < 4; kt++) {
            uint32_t af[4];
            ldsm4(af, pAddr[kt]);
#pragma unroll
            for (int ntp = 0; ntp < 4; ntp++) {
                uint32_t bq[4];
                ldsm4t(bq, Vs_b + 4 * ((kt * 16 + rowoff) * FS3 + ntp * 8 + kxw));
                mmah(o[2 * ntp],     af, bq[0], bq[1]);
                mmah(o[2 * ntp + 1], af, bq[2], bq[3]);
            }
        }
    }
#undef KVLOAD

    const float inv0 = 1.f / l0, inv1 = 1.f / l1;
    const int yrow0 = b * TSEQ + m0g + warp * 16 + gid;
#pragma unroll
    for (int nt = 0; nt < 8; nt++) {
        int c = h * DK + nt * 8 + tig * 2;
        *(uint32_t*)&y[(size_t)yrow0 * D_MODEL + c] =
            h2(o[nt][0] * inv0, o[nt][1] * inv0);
        *(uint32_t*)&y[(size_t)(yrow0 + 8) * D_MODEL + c] =
            h2(o[nt][2] * inv1, o[nt][3] * inv1);
    }
}

// ---------------------------------------------------------------------------
// launch
// ---------------------------------------------------------------------------
extern "C" void kernel_launch(void* const* d_in, const int* in_sizes, int n_in,
                              void* d_out, int out_size)
{
    const float* x      = (const float*)d_in[0];
    const float* W_attn = (const float*)d_in[1];
    const float* b_attn = (const float*)d_in[2];
    const float* W_o    = (const float*)d_in[3];
    const float* b_o    = (const float*)d_in[4];
    float* out = (float*)d_out;

    __half *hx, *hw, *hwo, *hqkv, *hy;
    cudaGetSymbolAddress((void**)&hx,   g_hx);
    cudaGetSymbolAddress((void**)&hw,   g_hw);
    cudaGetSymbolAddress((void**)&hwo,  g_hwo);
    cudaGetSymbolAddress((void**)&hqkv, g_qkv);
    cudaGetSymbolAddress((void**)&hy,   g_hy);

    // 0) one-time fp32 -> fp16 converts
    f2h<<<(BT * D_MODEL) / 2048, 256>>>(x, hx, BT * D_MODEL);
    f2h<<<(C3 * D_MODEL) / 2048, 256>>>(W_attn, hw, C3 * D_MODEL);
    f2h<<<(D_MODEL * D_MODEL) / 2048, 256>>>(W_o, hwo, D_MODEL * D_MODEL);

    cudaFuncSetAttribute(gemm_f16<true>,
                         cudaFuncAttributeMaxDynamicSharedMemorySize, GEMM_SMEM_B);
    cudaFuncSetAttribute(gemm_f16<false>,
                         cudaFuncAttributeMaxDynamicSharedMemorySize, GEMM_SMEM_B);
    cudaFuncSetAttribute(flash_attn_f16,
                         cudaFuncAttributeMaxDynamicSharedMemorySize, FL_SMEM_B);

    // 1) QKV projection: [8192,1024] @ [3072,1024]^T + b -> fp16 [8192,3072]
    gemm_f16<true><<<dim3(C3 / 128, BT / 128), 512, GEMM_SMEM_B>>>(
        hx, hw, b_attn, hqkv, BT, C3, D_MODEL);

    // 2) causal flash attention -> fp16 y [8192,1024]
    flash_attn_f16<<<dim3(TSEQ / 128, BATCH * NH), 256, FL_SMEM_B>>>(hqkv, hy);

    // 3) output projection: [8192,1024] @ [1024,1024]^T + b -> fp32 out
    gemm_f16<false><<<dim3(D_MODEL / 128, BT / 128), 512, GEMM_SMEM_B>>>(
        hy, hwo, b_o, out, BT, D_MODEL, D_MODEL);
}

// round 16
// speedup vs baseline: 1.1631x; 1.0650x over previous
#include <cuda_runtime.h>
#include <cuda_fp16.h>
#include <math.h>
#include <stdint.h>

// Problem constants
#define D_MODEL 1024
#define NH      16
#define DK      64
#define BATCH   4
#define TSEQ    2048
#define BT      (BATCH * TSEQ)      // 8192 rows
#define C3      (3 * D_MODEL)       // 3072

// Scratch (allocation-free rule: __device__ globals), all fp16
__device__ __half g_hx[BT * D_MODEL];        // 16 MB  x
__device__ __half g_hw[C3 * D_MODEL];        //  6 MB  W_attn
__device__ __half g_hwo[D_MODEL * D_MODEL];  //  2 MB  W_o
__device__ __half g_qkv[BT * C3];            // 48 MB  QKV
__device__ __half g_hy[BT * D_MODEL];        // 16 MB  attention out

// ---------------------------------------------------------------------------
// helpers
// ---------------------------------------------------------------------------
__device__ __forceinline__ uint32_t h2(float lo, float hi) {
    uint32_t r;
    asm("cvt.rn.f16x2.f32 %0, %1, %2;" : "=r"(r) : "f"(hi), "f"(lo));
    return r;
}

// packed half2 2^x (one SFU op for two values)
__device__ __forceinline__ uint32_t ex2h2(uint32_t x) {
    uint32_t r;
    asm("ex2.approx.f16x2 %0, %1;" : "=r"(r) : "r"(x));
    return r;
}

__device__ __forceinline__ void mmah(float c[4], const uint32_t a[4],
                                     uint32_t b0, uint32_t b1) {
    asm volatile(
        "mma.sync.aligned.m16n8k16.row.col.f32.f16.f16.f32 "
        "{%0,%1,%2,%3},{%4,%5,%6,%7},{%8,%9},{%0,%1,%2,%3};"
        : "+f"(c[0]), "+f"(c[1]), "+f"(c[2]), "+f"(c[3])
        : "r"(a[0]), "r"(a[1]), "r"(a[2]), "r"(a[3]), "r"(b0), "r"(b1));
}

__device__ __forceinline__ void ldsm4(uint32_t f[4], uint32_t addr) {
    asm volatile("ldmatrix.sync.aligned.m8n8.x4.shared.b16 {%0,%1,%2,%3}, [%4];"
        : "=r"(f[0]), "=r"(f[1]), "=r"(f[2]), "=r"(f[3]) : "r"(addr));
}

__device__ __forceinline__ void ldsm4t(uint32_t f[4], uint32_t addr) {
    asm volatile("ldmatrix.sync.aligned.m8n8.x4.trans.shared.b16 {%0,%1,%2,%3}, [%4];"
        : "=r"(f[0]), "=r"(f[1]), "=r"(f[2]), "=r"(f[3]) : "r"(addr));
}

__device__ __forceinline__ uint32_t smem_u32(const void* p) {
    return (uint32_t)__cvta_generic_to_shared(p);
}

__device__ __forceinline__ void cp16(uint32_t dst, const void* src) {
    asm volatile("cp.async.cg.shared.global [%0], [%1], 16;"
                 :: "r"(dst), "l"(src) : "memory");
}
#define CP_COMMIT() asm volatile("cp.async.commit_group;" ::: "memory")
#define CP_WAIT(n)  asm volatile("cp.async.wait_group %0;" :: "n"(n) : "memory")

// ---------------------------------------------------------------------------
// fp32 -> fp16 convert (8 elems/thread)
// ---------------------------------------------------------------------------
__global__ __launch_bounds__(256) void f2h(
    const float* __restrict__ in, __half* __restrict__ out, int n)
{
    int i = (blockIdx.x * 256 + threadIdx.x) * 8;
    if (i < n) {
        float4 a = *(const float4*)(in + i);
        float4 b = *(const float4*)(in + i + 4);
        uint4 t;
        t.x = h2(a.x, a.y); t.y = h2(a.z, a.w);
        t.z = h2(b.x, b.y); t.w = h2(b.z, b.w);
        *(uint4*)(out + i) = t;
    }
}

// ---------------------------------------------------------------------------
// FP16 tensor-core GEMM (NT): C[m][n] = sum_k A[m][k]*B[n][k] + bias[n]
// CTA tile 128(M) x 64(N), 256 threads = 8 warps (4m x 2n), warp tile 32x32.
// BK=64, 2-stage ring, TWO barriers per chunk: refill of stage s happens
// strictly AFTER the consumption barrier (fixes the R15 data race).
// __launch_bounds__(256,3) -> 3 CTAs/SM (24 warps) to cover latency.
// Rows of 64 halves, stride 36 words (9r mod 8 -> LDSM conflict-free).
// ---------------------------------------------------------------------------
#define GS2 36
#define AWRD (128 * GS2)              // A words per stage (4608)
#define BWRD (64 * GS2)               // B words per stage (2304)
#define GSTG3 (AWRD + BWRD)           // words per stage = 6912
#define GEMM_SMEM_B (2 * GSTG3 * 4)   // 55296 bytes

template<bool OUTH>
__global__ __launch_bounds__(256, 3) void gemm_f16(
    const __half* __restrict__ A, const __half* __restrict__ B,
    const float* __restrict__ bias, void* __restrict__ Cout,
    int M, int N, int K)
{
    extern __shared__ uint32_t gsm[];
    const uint32_t smb = smem_u32(gsm);

    const int tid  = threadIdx.x;
    const int warp = tid >> 5;
    const int lane = tid & 31;
    const int gid  = lane >> 2;
    const int tig  = lane & 3;
    const int wm   = warp >> 1;   // 0..3  (M)
    const int wn   = warp & 1;    // 0..1  (N)
    const int bm   = blockIdx.y * 128;
    const int bn   = blockIdx.x * 64;

    // loader: per stage A = 128 rows x 8 chunks (1024), B = 64 x 8 (512);
    // thread does A rows lr+{0,32,64,96}, B rows lr+{0,32} at chunk fj
    const int lr = tid >> 3;            // 0..31
    const int fj = tid & 7;
    const __half* Ag[4];
    const __half* Bg[2];
    uint32_t dA[4], dB[2];
#pragma unroll
    for (int i = 0; i < 4; i++) {
        Ag[i] = A + (size_t)(bm + lr + 32 * i) * K + fj * 8;
        dA[i] = (uint32_t)(((lr + 32 * i) * GS2 + fj * 4) * 4);
    }
#pragma unroll
    for (int i = 0; i < 2; i++) {
        Bg[i] = B + (size_t)(bn + lr + 32 * i) * K + fj * 8;
        dB[i] = (uint32_t)((AWRD + (lr + 32 * i) * GS2 + fj * 4) * 4);
    }

#define GLOAD(c, s) do {                                                     \
    uint32_t base = smb + (uint32_t)((s) * GSTG3) * 4;                       \
    size_t ko = (size_t)(c) * 64;                                            \
    cp16(base + dA[0], Ag[0] + ko); cp16(base + dA[1], Ag[1] + ko);          \
    cp16(base + dA[2], Ag[2] + ko); cp16(base + dA[3], Ag[3] + ko);          \
    cp16(base + dB[0], Bg[0] + ko); cp16(base + dB[1], Bg[1] + ko);          \
    CP_COMMIT(); } while (0)

    const int rowoff = ((lane >> 3) & 1) * 8 + (lane & 7);
    const int kxw    = (lane >> 4) * 4;

    uint32_t aBase[2], bBase[2];
#pragma unroll
    for (int mt = 0; mt < 2; mt++)
        aBase[mt] = (uint32_t)(((wm * 32 + mt * 16 + rowoff) * GS2 + kxw) * 4);
#pragma unroll
    for (int np = 0; np < 2; np++)
        bBase[np] = (uint32_t)((AWRD + (wn * 32 + np * 16 + rowoff) * GS2 + kxw) * 4);

    float acc[2][4][4];
#pragma unroll
    for (int i = 0; i < 2; i++)
#pragma unroll
        for (int j = 0; j < 4; j++)
#pragma unroll
            for (int e = 0; e < 4; e++) acc[i][j][e] = 0.f;

    const int nch = K >> 6;   // 16
    GLOAD(0, 0);              // group for chunk 0 -> stage 0
    GLOAD(1, 1);              // group for chunk 1 -> stage 1

    uint32_t af[2][2][4], bq[2][2][4];   // [buf][tile][frag]

    for (int c = 0; c < nch; c++) {
        const int s = c & 1;
        // Data-ready barrier: at most one younger group (chunk c+1) may
        // remain in flight; chunk c's group must be complete.
        if (c + 1 < nch) CP_WAIT(1);
        else             CP_WAIT(0);
        __syncthreads();

        const uint32_t sb = smb + (uint32_t)(s * GSTG3) * 4;

        // fill fragment buffer 0 (ks = 0)
        ldsm4(af[0][0], sb + aBase[0]);
        ldsm4(af[0][1], sb + aBase[1]);
        ldsm4(bq[0][0], sb + bBase[0]);
        ldsm4(bq[0][1], sb + bBase[1]);

#pragma unroll
        for (int ks = 0; ks < 4; ks++) {
            const int cur = ks & 1, nxt = cur ^ 1;
            if (ks < 3) {   // prefetch ks+1 fragments during MMAs
                const uint32_t o = (uint32_t)((ks + 1) * 32);
                ldsm4(af[nxt][0], sb + aBase[0] + o);
                ldsm4(af[nxt][1], sb + aBase[1] + o);
                ldsm4(bq[nxt][0], sb + bBase[0] + o);
                ldsm4(bq[nxt][1], sb + bBase[1] + o);
            }
#pragma unroll
            for (int mt = 0; mt < 2; mt++)
#pragma unroll
                for (int np = 0; np < 2; np++) {
                    mmah(acc[mt][2 * np],     af[cur][mt], bq[cur][np][0], bq[cur][np][2]);
                    mmah(acc[mt][2 * np + 1], af[cur][mt], bq[cur][np][1], bq[cur][np][3]);
                }
        }

        // Consumption barrier: every warp finished reading stage s.
        __syncthreads();
        // Only now is it safe to overwrite stage s with chunk c+2.
        if (c + 2 < nch) GLOAD(c + 2, s);
    }
#undef GLOAD

    // epilogue
#pragma unroll
    for (int mt = 0; mt < 2; mt++) {
        int r0 = bm + wm * 32 + mt * 16 + gid;
#pragma unroll
        for (int nt = 0; nt < 4; nt++) {
            int c = bn + wn * 32 + nt * 8 + tig * 2;
            float2 b2 = *(const float2*)&bias[c];
            float vx0 = acc[mt][nt][0] + b2.x, vy0 = acc[mt][nt][1] + b2.y;
            float vx1 = acc[mt][nt][2] + b2.x, vy1 = acc[mt][nt][3] + b2.y;
            if (OUTH) {
                __half* Ch = (__half*)Cout;
                *(uint32_t*)&Ch[(size_t)r0 * N + c]       = h2(vx0, vy0);
                *(uint32_t*)&Ch[(size_t)(r0 + 8) * N + c] = h2(vx1, vy1);
            } else {
                float* Cf = (float*)Cout;
                *(float2*)&Cf[(size_t)r0 * N + c]       = make_float2(vx0, vy0);
                *(float2*)&Cf[(size_t)(r0 + 8) * N + c] = make_float2(vx1, vy1);
            }
        }
    }
}

// ---------------------------------------------------------------------------
// FP16 flash attention (causal). Softmax exp via ex2.approx.f16x2. (R14, proven)
// ---------------------------------------------------------------------------
#define FS3 36
#define PS_W (128 * FS3)           // 4608 words
#define KV_W (64 * FS3)            // 2304 words
#define FL_SMEM_B ((PS_W + 4 * KV_W) * 4)   // 55296 bytes

__global__ __launch_bounds__(256) void flash_attn_f16(
    const __half* __restrict__ qkv, __half* __restrict__ y)
{
    extern __shared__ uint32_t sm[];
    uint32_t* Ps = sm;   // [q=128][64 halves] (Q staging, then P)

    const int tid  = threadIdx.x;
    const int warp = tid >> 5;
    const int lane = tid & 31;
    const int gid  = lane >> 2;
    const int tig  = lane & 3;

    const int rowoff = ((lane >> 3) & 1) * 8 + (lane & 7);
    const int kxw    = (lane >> 4) * 4;

    const uint32_t smb  = smem_u32(sm);
    const uint32_t kvb0 = smb + (uint32_t)PS_W * 4;

    const int qblk = (gridDim.x - 1) - blockIdx.x;   // big blocks first
    const int b    = blockIdx.y >> 4;
    const int h    = blockIdx.y & 15;

    const __half* base  = qkv + (size_t)b * TSEQ * C3 + h * DK;
    const int m0g = qblk * 128;
    const __half* baseQ = base + (size_t)m0g * C3;
    const __half* baseK = base + D_MODEL;
    const __half* baseV = base + 2 * D_MODEL;

    const int fr0 = tid >> 3;    // 0..31
    const int fj  = tid & 7;
    const uint32_t kv_d0 = (fr0 * FS3 + fj * 4) * 4;
    const uint32_t kv_d1 = ((fr0 + 32) * FS3 + fj * 4) * 4;

#define KVLOAD(kb, buf) do {                                                  \
    uint32_t kd = kvb0 + (uint32_t)((buf) * 2 * KV_W) * 4;                    \
    uint32_t vd = kd + (uint32_t)KV_W * 4;                                    \
    size_t ko = (size_t)((kb) * 64) * C3;                                     \
    cp16(kd + kv_d0, baseK + ko + (size_t)fr0 * C3 + fj * 8);                 \
    cp16(kd + kv_d1, baseK + ko + (size_t)(fr0 + 32) * C3 + fj * 8);          \
    cp16(vd + kv_d0, baseV + ko + (size_t)fr0 * C3 + fj * 8);                 \
    cp16(vd + kv_d1, baseV + ko + (size_t)(fr0 + 32) * C3 + fj * 8);          \
    CP_COMMIT(); } while (0)

#pragma unroll
    for (int i = 0; i < 4; i++) {
        int row = fr0 + 32 * i;
        cp16(smb + (uint32_t)((row * FS3 + fj * 4) * 4),
             baseQ + (size_t)row * C3 + fj * 8);
    }
    KVLOAD(0, 0);
    CP_WAIT(0);
    __syncthreads();

    uint32_t pAddr[4];
#pragma unroll
    for (int kt = 0; kt < 4; kt++)
        pAddr[kt] = smb + 4 * ((warp * 16 + rowoff) * FS3 + kt * 8 + kxw);

    uint32_t qf[4][4];
#pragma unroll
    for (int kt = 0; kt < 4; kt++) ldsm4(qf[kt], pAddr[kt]);

    float o[8][4];
#pragma unroll
    for (int nt = 0; nt < 8; nt++)
#pragma unroll
        for (int e = 0; e < 4; e++) o[nt][e] = 0.f;
    float mx0 = -1e30f, mx1 = -1e30f, l0 = 0.f, l1 = 0.f;

    const int rglob0 = m0g + warp * 16 + gid;
    const int rglob1 = rglob0 + 8;
    const int nkb = 2 * qblk + 2;
    const float L2E = 1.4426950408889634f;   // log2(e)

    for (int kb = 0; kb < nkb; kb++) {
        const int s = kb & 1;
        if (kb > 0) CP_WAIT(0);
        __syncthreads();
        if (kb + 1 < nkb) KVLOAD(kb + 1, 1 - s);

        const uint32_t Ks_b = kvb0 + (uint32_t)(s * 2 * KV_W) * 4;
        const uint32_t Vs_b = Ks_b + (uint32_t)KV_W * 4;

        float sc[8][4];
#pragma unroll
        for (int nt = 0; nt < 8; nt++)
#pragma unroll
            for (int e = 0; e < 4; e++) sc[nt][e] = 0.f;

#pragma unroll
        for (int kt = 0; kt < 4; kt++) {
#pragma unroll
            for (int ntp = 0; ntp < 4; ntp++) {
                uint32_t bq[4];
                ldsm4(bq, Ks_b + 4 * ((ntp * 16 + rowoff) * FS3 + kt * 8 + kxw));
                mmah(sc[2 * ntp],     qf[kt], bq[0], bq[2]);
                mmah(sc[2 * ntp + 1], qf[kt], bq[1], bq[3]);
            }
        }

        const float scale = 0.125f;
        if (kb >= 2 * qblk) {
#pragma unroll
            for (int nt = 0; nt < 8; nt++) {
                int c0 = kb * 64 + nt * 8 + tig * 2;
                sc[nt][0] = (c0     > rglob0) ? -1e30f : sc[nt][0] * scale;
                sc[nt][1] = (c0 + 1 > rglob0) ? -1e30f : sc[nt][1] * scale;
                sc[nt][2] = (c0     > rglob1) ? -1e30f : sc[nt][2] * scale;
                sc[nt][3] = (c0 + 1 > rglob1) ? -1e30f : sc[nt][3] * scale;
            }
        } else {
#pragma unroll
            for (int nt = 0; nt < 8; nt++)
#pragma unroll
                for (int e = 0; e < 4; e++) sc[nt][e] *= scale;
        }

        float vm0 = -1e30f, vm1 = -1e30f;
#pragma unroll
        for (int nt = 0; nt < 8; nt++) {
            vm0 = fmaxf(vm0, fmaxf(sc[nt][0], sc[nt][1]));
            vm1 = fmaxf(vm1, fmaxf(sc[nt][2], sc[nt][3]));
        }
        vm0 = fmaxf(vm0, __shfl_xor_sync(0xffffffffu, vm0, 1));
        vm0 = fmaxf(vm0, __shfl_xor_sync(0xffffffffu, vm0, 2));
        vm1 = fmaxf(vm1, __shfl_xor_sync(0xffffffffu, vm1, 1));
        vm1 = fmaxf(vm1, __shfl_xor_sync(0xffffffffu, vm1, 2));

        float nm0 = fmaxf(mx0, vm0), nm1 = fmaxf(mx1, vm1);
        float al0 = __expf(mx0 - nm0), al1 = __expf(mx1 - nm1);

        const float nm0L = nm0 * L2E, nm1L = nm1 * L2E;
        uint32_t ph[8][2];
        float sum0 = 0.f, sum1 = 0.f;
#pragma unroll
        for (int nt = 0; nt < 8; nt++) {
            uint32_t a0 = h2(fmaf(sc[nt][0], L2E, -nm0L),
                             fmaf(sc[nt][1], L2E, -nm0L));
            uint32_t a1 = h2(fmaf(sc[nt][2], L2E, -nm1L),
                             fmaf(sc[nt][3], L2E, -nm1L));
            ph[nt][0] = ex2h2(a0);
            ph[nt][1] = ex2h2(a1);
            float2 p0 = __half22float2(*(__half2*)&ph[nt][0]);
            float2 p1 = __half22float2(*(__half2*)&ph[nt][1]);
            sum0 += p0.x + p0.y;
            sum1 += p1.x + p1.y;
        }
        sum0 += __shfl_xor_sync(0xffffffffu, sum0, 1);
        sum0 += __shfl_xor_sync(0xffffffffu, sum0, 2);
        sum1 += __shfl_xor_sync(0xffffffffu, sum1, 1);
        sum1 += __shfl_xor_sync(0xffffffffu, sum1, 2);

        l0 = l0 * al0 + sum0;  mx0 = nm0;
        l1 = l1 * al1 + sum1;  mx1 = nm1;

#pragma unroll
        for (int nt = 0; nt < 8; nt++) {
            o[nt][0] *= al0; o[nt][1] *= al0;
            o[nt][2] *= al1; o[nt][3] *= al1;
        }

        {
            const int rl0 = warp * 16 + gid;
#pragma unroll
            for (int nt = 0; nt < 8; nt++) {
                Ps[rl0 * FS3 + nt * 4 + tig]       = ph[nt][0];
                Ps[(rl0 + 8) * FS3 + nt * 4 + tig] = ph[nt][1];
            }
        }
        __syncwarp();

#pragma unroll
        for (int kt = 0; kt < 4; kt++) {
            uint32_t af[4];
            ldsm4(af, pAddr[kt]);
#pragma unroll
            for (int ntp = 0; ntp < 4; ntp++) {
                uint32_t bq[4];
                ldsm4t(bq, Vs_b + 4 * ((kt * 16 + rowoff) * FS3 + ntp * 8 + kxw));
                mmah(o[2 * ntp],     af, bq[0], bq[1]);
                mmah(o[2 * ntp + 1], af, bq[2], bq[3]);
            }
        }
    }
#undef KVLOAD

    const float inv0 = 1.f / l0, inv1 = 1.f / l1;
    const int yrow0 = b * TSEQ + m0g + warp * 16 + gid;
#pragma unroll
    for (int nt = 0; nt < 8; nt++) {
        int c = h * DK + nt * 8 + tig * 2;
        *(uint32_t*)&y[(size_t)yrow0 * D_MODEL + c] =
            h2(o[nt][0] * inv0, o[nt][1] * inv0);
        *(uint32_t*)&y[(size_t)(yrow0 + 8) * D_MODEL + c] =
            h2(o[nt][2] * inv1, o[nt][3] * inv1);
    }
}

// ---------------------------------------------------------------------------
// launch
// ---------------------------------------------------------------------------
extern "C" void kernel_launch(void* const* d_in, const int* in_sizes, int n_in,
                              void* d_out, int out_size)
{
    const float* x      = (const float*)d_in[0];
    const float* W_attn = (const float*)d_in[1];
    const float* b_attn = (const float*)d_in[2];
    const float* W_o    = (const float*)d_in[3];
    const float* b_o    = (const float*)d_in[4];
    float* out = (float*)d_out;

    __half *hx, *hw, *hwo, *hqkv, *hy;
    cudaGetSymbolAddress((void**)&hx,   g_hx);
    cudaGetSymbolAddress((void**)&hw,   g_hw);
    cudaGetSymbolAddress((void**)&hwo,  g_hwo);
    cudaGetSymbolAddress((void**)&hqkv, g_qkv);
    cudaGetSymbolAddress((void**)&hy,   g_hy);

    // 0) one-time fp32 -> fp16 converts
    f2h<<<(BT * D_MODEL) / 2048, 256>>>(x, hx, BT * D_MODEL);
    f2h<<<(C3 * D_MODEL) / 2048, 256>>>(W_attn, hw, C3 * D_MODEL);
    f2h<<<(D_MODEL * D_MODEL) / 2048, 256>>>(W_o, hwo, D_MODEL * D_MODEL);

    cudaFuncSetAttribute(gemm_f16<true>,
                         cudaFuncAttributeMaxDynamicSharedMemorySize, GEMM_SMEM_B);
    cudaFuncSetAttribute(gemm_f16<false>,
                         cudaFuncAttributeMaxDynamicSharedMemorySize, GEMM_SMEM_B);
    cudaFuncSetAttribute(flash_attn_f16,
                         cudaFuncAttributeMaxDynamicSharedMemorySize, FL_SMEM_B);

    // 1) QKV projection: [8192,1024] @ [3072,1024]^T + b -> fp16 [8192,3072]
    gemm_f16<true><<<dim3(C3 / 64, BT / 128), 256, GEMM_SMEM_B>>>(
        hx, hw, b_attn, hqkv, BT, C3, D_MODEL);

    // 2) causal flash attention -> fp16 y [8192,1024]
    flash_attn_f16<<<dim3(TSEQ / 128, BATCH * NH), 256, FL_SMEM_B>>>(hqkv, hy);

    // 3) output projection: [8192,1024] @ [1024,1024]^T + b -> fp32 out
    gemm_f16<false><<<dim3(D_MODEL / 64, BT / 128), 256, GEMM_SMEM_B>>>(
        hy, hwo, b_o, out, BT, D_MODEL, D_MODEL);
}

// round 17
// speedup vs baseline: 1.1638x; 1.0006x over previous
#include <cuda_runtime.h>
#include <cuda_fp16.h>
#include <math.h>
#include <stdint.h>

// Problem constants
#define D_MODEL 1024
#define NH      16
#define DK      64
#define BATCH   4
#define TSEQ    2048
#define BT      (BATCH * TSEQ)      // 8192 rows
#define C3      (3 * D_MODEL)       // 3072

// Scratch (allocation-free rule: __device__ globals), all fp16
__device__ __half g_hx[BT * D_MODEL];        // 16 MB  x
__device__ __half g_hw[C3 * D_MODEL];        //  6 MB  W_attn
__device__ __half g_hwo[D_MODEL * D_MODEL];  //  2 MB  W_o
__device__ __half g_qkv[BT * C3];            // 48 MB  QKV
__device__ __half g_hy[BT * D_MODEL];        // 16 MB  attention out

// ---------------------------------------------------------------------------
// helpers
// ---------------------------------------------------------------------------
__device__ __forceinline__ uint32_t h2(float lo, float hi) {
    uint32_t r;
    asm("cvt.rn.f16x2.f32 %0, %1, %2;" : "=r"(r) : "f"(hi), "f"(lo));
    return r;
}

// packed half2 2^x (one SFU op for two values)
__device__ __forceinline__ uint32_t ex2h2(uint32_t x) {
    uint32_t r;
    asm("ex2.approx.f16x2 %0, %1;" : "=r"(r) : "r"(x));
    return r;
}

__device__ __forceinline__ void mmah(float c[4], const uint32_t a[4],
                                     uint32_t b0, uint32_t b1) {
    asm volatile(
        "mma.sync.aligned.m16n8k16.row.col.f32.f16.f16.f32 "
        "{%0,%1,%2,%3},{%4,%5,%6,%7},{%8,%9},{%0,%1,%2,%3};"
        : "+f"(c[0]), "+f"(c[1]), "+f"(c[2]), "+f"(c[3])
        : "r"(a[0]), "r"(a[1]), "r"(a[2]), "r"(a[3]), "r"(b0), "r"(b1));
}

__device__ __forceinline__ void ldsm4(uint32_t f[4], uint32_t addr) {
    asm volatile("ldmatrix.sync.aligned.m8n8.x4.shared.b16 {%0,%1,%2,%3}, [%4];"
        : "=r"(f[0]), "=r"(f[1]), "=r"(f[2]), "=r"(f[3]) : "r"(addr));
}

__device__ __forceinline__ void ldsm4t(uint32_t f[4], uint32_t addr) {
    asm volatile("ldmatrix.sync.aligned.m8n8.x4.trans.shared.b16 {%0,%1,%2,%3}, [%4];"
        : "=r"(f[0]), "=r"(f[1]), "=r"(f[2]), "=r"(f[3]) : "r"(addr));
}

__device__ __forceinline__ uint32_t smem_u32(const void* p) {
    return (uint32_t)__cvta_generic_to_shared(p);
}

__device__ __forceinline__ void cp16(uint32_t dst, const void* src) {
    asm volatile("cp.async.cg.shared.global [%0], [%1], 16;"
                 :: "r"(dst), "l"(src) : "memory");
}
#define CP_COMMIT() asm volatile("cp.async.commit_group;" ::: "memory")
#define CP_WAIT(n)  asm volatile("cp.async.wait_group %0;" :: "n"(n) : "memory")

// ---------------------------------------------------------------------------
// fp32 -> fp16 convert (8 elems/thread)
// ---------------------------------------------------------------------------
__global__ __launch_bounds__(256) void f2h(
    const float* __restrict__ in, __half* __restrict__ out, int n)
{
    int i = (blockIdx.x * 256 + threadIdx.x) * 8;
    if (i < n) {
        float4 a = *(const float4*)(in + i);
        float4 b = *(const float4*)(in + i + 4);
        uint4 t;
        t.x = h2(a.x, a.y); t.y = h2(a.z, a.w);
        t.z = h2(b.x, b.y); t.w = h2(b.z, b.w);
        *(uint4*)(out + i) = t;
    }
}

// ---------------------------------------------------------------------------
// FP16 tensor-core GEMM (NT): C[m][n] = sum_k A[m][k]*B[n][k] + bias[n]
// CTA tile 128(M) x 64(N), 256 threads = 8 warps (4m x 2n), warp tile 32x32.
// BK=64, 2-stage ring, two barriers per chunk (refill strictly after the
// consumption barrier). Single-buffered fragments + compact loader indexing
// to fit 64 regs -> __launch_bounds__(256,4): 4 CTAs/SM, 32 warps.
// Rows of 64 halves, stride 36 words (9r mod 8 -> LDSM conflict-free).
// ---------------------------------------------------------------------------
#define GS2 36
#define AWRD (128 * GS2)              // A words per stage (4608)
#define BWRD (64 * GS2)               // B words per stage (2304)
#define GSTG3 (AWRD + BWRD)           // words per stage = 6912
#define GEMM_SMEM_B (2 * GSTG3 * 4)   // 55296 bytes
#define AROWB (32 * GS2 * 4)          // dest offset per 32 rows = 4608 bytes

template<bool OUTH>
__global__ __launch_bounds__(256, 4) void gemm_f16(
    const __half* __restrict__ A, const __half* __restrict__ B,
    const float* __restrict__ bias, void* __restrict__ Cout,
    int M, int N, int K)
{
    extern __shared__ uint32_t gsm[];
    const uint32_t smb = smem_u32(gsm);

    const int tid  = threadIdx.x;
    const int warp = tid >> 5;
    const int lane = tid & 31;
    const int gid  = lane >> 2;
    const int tig  = lane & 3;
    const int wm   = warp >> 1;   // 0..3  (M)
    const int wn   = warp & 1;    // 0..1  (N)
    const int bm   = blockIdx.y * 128;
    const int bn   = blockIdx.x * 64;

    // loader: thread covers A rows lr+{0,32,64,96}, B rows lr+{0,32} at
    // chunk fj. Sources differ by 32*K elems; dests by AROWB bytes.
    const int lr = tid >> 3;            // 0..31
    const int fj = tid & 7;
    const __half* Ag = A + (size_t)(bm + lr) * K + fj * 8;
    const __half* Bg = B + (size_t)(bn + lr) * K + fj * 8;
    const size_t k32 = (size_t)32 * K;
    const uint32_t dA0 = (uint32_t)((lr * GS2 + fj * 4) * 4);
    const uint32_t dB0 = (uint32_t)(AWRD * 4) + dA0;

#define GLOAD(c, s) do {                                                     \
    uint32_t base = smb + (uint32_t)((s) * GSTG3) * 4;                       \
    const __half* ap = Ag + (size_t)(c) * 64;                                \
    const __half* bp = Bg + (size_t)(c) * 64;                                \
    cp16(base + dA0,             ap);                                        \
    cp16(base + dA0 + AROWB,     ap + k32);                                  \
    cp16(base + dA0 + 2 * AROWB, ap + 2 * k32);                              \
    cp16(base + dA0 + 3 * AROWB, ap + 3 * k32);                              \
    cp16(base + dB0,             bp);                                        \
    cp16(base + dB0 + AROWB,     bp + k32);                                  \
    CP_COMMIT(); } while (0)

    const int rowoff = ((lane >> 3) & 1) * 8 + (lane & 7);
    const int kxw    = (lane >> 4) * 4;

    uint32_t aBase[2], bBase[2];
#pragma unroll
    for (int mt = 0; mt < 2; mt++)
        aBase[mt] = (uint32_t)(((wm * 32 + mt * 16 + rowoff) * GS2 + kxw) * 4);
#pragma unroll
    for (int np = 0; np < 2; np++)
        bBase[np] = (uint32_t)((AWRD + (wn * 32 + np * 16 + rowoff) * GS2 + kxw) * 4);

    float acc[2][4][4];
#pragma unroll
    for (int i = 0; i < 2; i++)
#pragma unroll
        for (int j = 0; j < 4; j++)
#pragma unroll
            for (int e = 0; e < 4; e++) acc[i][j][e] = 0.f;

    const int nch = K >> 6;   // 16
    GLOAD(0, 0);              // chunk 0 -> stage 0
    GLOAD(1, 1);              // chunk 1 -> stage 1

    for (int c = 0; c < nch; c++) {
        const int s = c & 1;
        // Data-ready barrier: chunk c's group complete (<=1 younger pending).
        if (c + 1 < nch) CP_WAIT(1);
        else             CP_WAIT(0);
        __syncthreads();

        const uint32_t sb = smb + (uint32_t)(s * GSTG3) * 4;

#pragma unroll
        for (int ks = 0; ks < 4; ks++) {
            const uint32_t o = (uint32_t)(ks * 32);
            uint32_t af[2][4], bq[2][4];
            ldsm4(af[0], sb + aBase[0] + o);
            ldsm4(af[1], sb + aBase[1] + o);
            ldsm4(bq[0], sb + bBase[0] + o);
            ldsm4(bq[1], sb + bBase[1] + o);
#pragma unroll
            for (int mt = 0; mt < 2; mt++)
#pragma unroll
                for (int np = 0; np < 2; np++) {
                    mmah(acc[mt][2 * np],     af[mt], bq[np][0], bq[np][2]);
                    mmah(acc[mt][2 * np + 1], af[mt], bq[np][1], bq[np][3]);
                }
        }

        // Consumption barrier: all warps finished reading stage s.
        __syncthreads();
        if (c + 2 < nch) GLOAD(c + 2, s);   // safe to overwrite stage s now
    }
#undef GLOAD

    // epilogue
#pragma unroll
    for (int mt = 0; mt < 2; mt++) {
        int r0 = bm + wm * 32 + mt * 16 + gid;
#pragma unroll
        for (int nt = 0; nt < 4; nt++) {
            int c = bn + wn * 32 + nt * 8 + tig * 2;
            float2 b2 = *(const float2*)&bias[c];
            float vx0 = acc[mt][nt][0] + b2.x, vy0 = acc[mt][nt][1] + b2.y;
            float vx1 = acc[mt][nt][2] + b2.x, vy1 = acc[mt][nt][3] + b2.y;
            if (OUTH) {
                __half* Ch = (__half*)Cout;
                *(uint32_t*)&Ch[(size_t)r0 * N + c]       = h2(vx0, vy0);
                *(uint32_t*)&Ch[(size_t)(r0 + 8) * N + c] = h2(vx1, vy1);
            } else {
                float* Cf = (float*)Cout;
                *(float2*)&Cf[(size_t)r0 * N + c]       = make_float2(vx0, vy0);
                *(float2*)&Cf[(size_t)(r0 + 8) * N + c] = make_float2(vx1, vy1);
            }
        }
    }
}

// ---------------------------------------------------------------------------
// FP16 flash attention (causal). Softmax exp via ex2.approx.f16x2. (R14, proven)
// ---------------------------------------------------------------------------
#define FS3 36
#define PS_W (128 * FS3)           // 4608 words
#define KV_W (64 * FS3)            // 2304 words
#define FL_SMEM_B ((PS_W + 4 * KV_W) * 4)   // 55296 bytes

__global__ __launch_bounds__(256) void flash_attn_f16(
    const __half* __restrict__ qkv, __half* __restrict__ y)
{
    extern __shared__ uint32_t sm[];
    uint32_t* Ps = sm;   // [q=128][64 halves] (Q staging, then P)

    const int tid  = threadIdx.x;
    const int warp = tid >> 5;
    const int lane = tid & 31;
    const int gid  = lane >> 2;
    const int tig  = lane & 3;

    const int rowoff = ((lane >> 3) & 1) * 8 + (lane & 7);
    const int kxw    = (lane >> 4) * 4;

    const uint32_t smb  = smem_u32(sm);
    const uint32_t kvb0 = smb + (uint32_t)PS_W * 4;

    const int qblk = (gridDim.x - 1) - blockIdx.x;   // big blocks first
    const int b    = blockIdx.y >> 4;
    const int h    = blockIdx.y & 15;

    const __half* base  = qkv + (size_t)b * TSEQ * C3 + h * DK;
    const int m0g = qblk * 128;
    const __half* baseQ = base + (size_t)m0g * C3;
    const __half* baseK = base + D_MODEL;
    const __half* baseV = base + 2 * D_MODEL;

    const int fr0 = tid >> 3;    // 0..31
    const int fj  = tid & 7;
    const uint32_t kv_d0 = (fr0 * FS3 + fj * 4) * 4;
    const uint32_t kv_d1 = ((fr0 + 32) * FS3 + fj * 4) * 4;

#define KVLOAD(kb, buf) do {                                                  \
    uint32_t kd = kvb0 + (uint32_t)((buf) * 2 * KV_W) * 4;                    \
    uint32_t vd = kd + (uint32_t)KV_W * 4;                                    \
    size_t ko = (size_t)((kb) * 64) * C3;                                     \
    cp16(kd + kv_d0, baseK + ko + (size_t)fr0 * C3 + fj * 8);                 \
    cp16(kd + kv_d1, baseK + ko + (size_t)(fr0 + 32) * C3 + fj * 8);          \
    cp16(vd + kv_d0, baseV + ko + (size_t)fr0 * C3 + fj * 8);                 \
    cp16(vd + kv_d1, baseV + ko + (size_t)(fr0 + 32) * C3 + fj * 8);          \
    CP_COMMIT(); } while (0)

#pragma unroll
    for (int i = 0; i < 4; i++) {
        int row = fr0 + 32 * i;
        cp16(smb + (uint32_t)((row * FS3 + fj * 4) * 4),
             baseQ + (size_t)row * C3 + fj * 8);
    }
    KVLOAD(0, 0);
    CP_WAIT(0);
    __syncthreads();

    uint32_t pAddr[4];
#pragma unroll
    for (int kt = 0; kt < 4; kt++)
        pAddr[kt] = smb + 4 * ((warp * 16 + rowoff) * FS3 + kt * 8 + kxw);

    uint32_t qf[4][4];
#pragma unroll
    for (int kt = 0; kt < 4; kt++) ldsm4(qf[kt], pAddr[kt]);

    float o[8][4];
#pragma unroll
    for (int nt = 0; nt < 8; nt++)
#pragma unroll
        for (int e = 0; e < 4; e++) o[nt][e] = 0.f;
    float mx0 = -1e30f, mx1 = -1e30f, l0 = 0.f, l1 = 0.f;

    const int rglob0 = m0g + warp * 16 + gid;
    const int rglob1 = rglob0 + 8;
    const int nkb = 2 * qblk + 2;
    const float L2E = 1.4426950408889634f;   // log2(e)

    for (int kb = 0; kb < nkb; kb++) {
        const int s = kb & 1;
        if (kb > 0) CP_WAIT(0);
        __syncthreads();
        if (kb + 1 < nkb) KVLOAD(kb + 1, 1 - s);

        const uint32_t Ks_b = kvb0 + (uint32_t)(s * 2 * KV_W) * 4;
        const uint32_t Vs_b = Ks_b + (uint32_t)KV_W * 4;

        float sc[8][4];
#pragma unroll
        for (int nt = 0; nt < 8; nt++)
#pragma unroll
            for (int e = 0; e < 4; e++) sc[nt][e] = 0.f;

#pragma unroll
        for (int kt = 0; kt < 4; kt++) {
#pragma unroll
            for (int ntp = 0; ntp < 4; ntp++) {
                uint32_t bq[4];
                ldsm4(bq, Ks_b + 4 * ((ntp * 16 + rowoff) * FS3 + kt * 8 + kxw));
                mmah(sc[2 * ntp],     qf[kt], bq[0], bq[2]);
                mmah(sc[2 * ntp + 1], qf[kt], bq[1], bq[3]);
            }
        }

        const float scale = 0.125f;
        if (kb >= 2 * qblk) {
#pragma unroll
            for (int nt = 0; nt < 8; nt++) {
                int c0 = kb * 64 + nt * 8 + tig * 2;
                sc[nt][0] = (c0     > rglob0) ? -1e30f : sc[nt][0] * scale;
                sc[nt][1] = (c0 + 1 > rglob0) ? -1e30f : sc[nt][1] * scale;
                sc[nt][2] = (c0     > rglob1) ? -1e30f : sc[nt][2] * scale;
                sc[nt][3] = (c0 + 1 > rglob1) ? -1e30f : sc[nt][3] * scale;
            }
        } else {
#pragma unroll
            for (int nt = 0; nt < 8; nt++)
#pragma unroll
                for (int e = 0; e < 4; e++) sc[nt][e] *= scale;
        }

        float vm0 = -1e30f, vm1 = -1e30f;
#pragma unroll
        for (int nt = 0; nt < 8; nt++) {
            vm0 = fmaxf(vm0, fmaxf(sc[nt][0], sc[nt][1]));
            vm1 = fmaxf(vm1, fmaxf(sc[nt][2], sc[nt][3]));
        }
        vm0 = fmaxf(vm0, __shfl_xor_sync(0xffffffffu, vm0, 1));
        vm0 = fmaxf(vm0, __shfl_xor_sync(0xffffffffu, vm0, 2));
        vm1 = fmaxf(vm1, __shfl_xor_sync(0xffffffffu, vm1, 1));
        vm1 = fmaxf(vm1, __shfl_xor_sync(0xffffffffu, vm1, 2));

        float nm0 = fmaxf(mx0, vm0), nm1 = fmaxf(mx1, vm1);
        float al0 = __expf(mx0 - nm0), al1 = __expf(mx1 - nm1);

        const float nm0L = nm0 * L2E, nm1L = nm1 * L2E;
        uint32_t ph[8][2];
        float sum0 = 0.f, sum1 = 0.f;
#pragma unroll
        for (int nt = 0; nt < 8; nt++) {
            uint32_t a0 = h2(fmaf(sc[nt][0], L2E, -nm0L),
                             fmaf(sc[nt][1], L2E, -nm0L));
            uint32_t a1 = h2(fmaf(sc[nt][2], L2E, -nm1L),
                             fmaf(sc[nt][3], L2E, -nm1L));
            ph[nt][0] = ex2h2(a0);
            ph[nt][1] = ex2h2(a1);
            float2 p0 = __half22float2(*(__half2*)&ph[nt][0]);
            float2 p1 = __half22float2(*(__half2*)&ph[nt][1]);
            sum0 += p0.x + p0.y;
            sum1 += p1.x + p1.y;
        }
        sum0 += __shfl_xor_sync(0xffffffffu, sum0, 1);
        sum0 += __shfl_xor_sync(0xffffffffu, sum0, 2);
        sum1 += __shfl_xor_sync(0xffffffffu, sum1, 1);
        sum1 += __shfl_xor_sync(0xffffffffu, sum1, 2);

        l0 = l0 * al0 + sum0;  mx0 = nm0;
        l1 = l1 * al1 + sum1;  mx1 = nm1;

#pragma unroll
        for (int nt = 0; nt < 8; nt++) {
            o[nt][0] *= al0; o[nt][1] *= al0;
            o[nt][2] *= al1; o[nt][3] *= al1;
        }

        {
            const int rl0 = warp * 16 + gid;
#pragma unroll
            for (int nt = 0; nt < 8; nt++) {
                Ps[rl0 * FS3 + nt * 4 + tig]       = ph[nt][0];
                Ps[(rl0 + 8) * FS3 + nt * 4 + tig] = ph[nt][1];
            }
        }
        __syncwarp();

#pragma unroll
        for (int kt = 0; kt < 4; kt++) {
            uint32_t af[4];
            ldsm4(af, pAddr[kt]);
#pragma unroll
            for (int ntp = 0; ntp < 4; ntp++) {
                uint32_t bq[4];
                ldsm4t(bq, Vs_b + 4 * ((kt * 16 + rowoff) * FS3 + ntp * 8 + kxw));
                mmah(o[2 * ntp],     af, bq[0], bq[1]);
                mmah(o[2 * ntp + 1], af, bq[2], bq[3]);
            }
        }
    }
#undef KVLOAD

    const float inv0 = 1.f / l0, inv1 = 1.f / l1;
    const int yrow0 = b * TSEQ + m0g + warp * 16 + gid;
#pragma unroll
    for (int nt = 0; nt < 8; nt++) {
        int c = h * DK + nt * 8 + tig * 2;
        *(uint32_t*)&y[(size_t)yrow0 * D_MODEL + c] =
            h2(o[nt][0] * inv0, o[nt][1] * inv0);
        *(uint32_t*)&y[(size_t)(yrow0 + 8) * D_MODEL + c] =
            h2(o[nt][2] * inv1, o[nt][3] * inv1);
    }
}

// ---------------------------------------------------------------------------
// launch
// ---------------------------------------------------------------------------
extern "C" void kernel_launch(void* const* d_in, const int* in_sizes, int n_in,
                              void* d_out, int out_size)
{
    const float* x      = (const float*)d_in[0];
    const float* W_attn = (const float*)d_in[1];
    const float* b_attn = (const float*)d_in[2];
    const float* W_o    = (const float*)d_in[3];
    const float* b_o    = (const float*)d_in[4];
    float* out = (float*)d_out;

    __half *hx, *hw, *hwo, *hqkv, *hy;
    cudaGetSymbolAddress((void**)&hx,   g_hx);
    cudaGetSymbolAddress((void**)&hw,   g_hw);
    cudaGetSymbolAddress((void**)&hwo,  g_hwo);
    cudaGetSymbolAddress((void**)&hqkv, g_qkv);
    cudaGetSymbolAddress((void**)&hy,   g_hy);

    // 0) one-time fp32 -> fp16 converts
    f2h<<<(BT * D_MODEL) / 2048, 256>>>(x, hx, BT * D_MODEL);
    f2h<<<(C3 * D_MODEL) / 2048, 256>>>(W_attn, hw, C3 * D_MODEL);
    f2h<<<(D_MODEL * D_MODEL) / 2048, 256>>>(W_o, hwo, D_MODEL * D_MODEL);

    cudaFuncSetAttribute(gemm_f16<true>,
                         cudaFuncAttributeMaxDynamicSharedMemorySize, GEMM_SMEM_B);
    cudaFuncSetAttribute(gemm_f16<false>,
                         cudaFuncAttributeMaxDynamicSharedMemorySize, GEMM_SMEM_B);
    cudaFuncSetAttribute(flash_attn_f16,
                         cudaFuncAttributeMaxDynamicSharedMemorySize, FL_SMEM_B);

    // 1) QKV projection: [8192,1024] @ [3072,1024]^T + b -> fp16 [8192,3072]
    gemm_f16<true><<<dim3(C3 / 64, BT / 128), 256, GEMM_SMEM_B>>>(
        hx, hw, b_attn, hqkv, BT, C3, D_MODEL);

    // 2) causal flash attention -> fp16 y [8192,1024]
    flash_attn_f16<<<dim3(TSEQ / 128, BATCH * NH), 256, FL_SMEM_B>>>(hqkv, hy);

    // 3) output projection: [8192,1024] @ [1024,1024]^T + b -> fp32 out
    gemm_f16<false><<<dim3(D_MODEL / 64, BT / 128), 256, GEMM_SMEM_B>>>(
        hy, hwo, b_o, out, BT, D_MODEL, D_MODEL);
}